// round 3
// baseline (speedup 1.0000x reference)
#include <cuda_runtime.h>
#include <float.h>

#define BATCH 8
#define C 512
#define HW 16384
#define KCLS 150
#define KPAD 160
#define NSPLIT 8

// ---------------- scratch (device globals; no allocations) ----------------
__device__ float g_E[BATCH * KCLS * HW];        // exp(coupled_attn)
__device__ float g_colinv[BATCH * HW];          // 1 / sum_k E
__device__ float g_rowpart[BATCH * KPAD * 256]; // per-n-tile partial row sums
__device__ float g_rinv[BATCH * KPAD];          // 1 / sum_n E
__device__ float g_poolpart[NSPLIT * BATCH * KPAD * C];
__device__ float g_acls[BATCH * KCLS * C];
__device__ float g_clsWf[KCLS * C];             // cls @ W_feat^T
__device__ float g_G[BATCH * KPAD * KPAD];      // acls @ clsWf^T (zero padded)

// ===========================================================================
// GEMM1: E[b,k,n] = exp( sum_c cls[k,c] * x[b,c,n] )
// Tile: BM=160 (all k), BN=64 (n), BK=32. 256 thr, 5x8 micro.
// Epilogue: colinv[b,n] (full, in-block) + rowpart[b,k,ntile].
// ===========================================================================
__global__ __launch_bounds__(256) void k_gemm1(
    const float* __restrict__ cls, const float* __restrict__ x,
    float* __restrict__ E, float* __restrict__ colinv, float* __restrict__ rowpart)
{
    __shared__ float As[32][161];   // [c][k]
    __shared__ float Bs[32][64];    // [c][n]
    const int t  = threadIdx.x;
    const int n0 = blockIdx.x * 64;
    const int b  = blockIdx.y;
    const int rt = t >> 3, ct = t & 7;
    const float* Xb = x + (long)b * C * HW;

    float acc[5][8] = {};
    for (int c0 = 0; c0 < C; c0 += 32) {
        #pragma unroll
        for (int i = 0; i < 5; ++i) {
            int f = t + 256 * i, row = f >> 3, c4 = (f & 7) * 4;
            float4 v = make_float4(0.f, 0.f, 0.f, 0.f);
            if (row < KCLS) v = *(const float4*)&cls[(long)row * C + c0 + c4];
            As[c4 + 0][row] = v.x; As[c4 + 1][row] = v.y;
            As[c4 + 2][row] = v.z; As[c4 + 3][row] = v.w;
        }
        #pragma unroll
        for (int i = 0; i < 2; ++i) {
            int f = t + 256 * i, r = f >> 4, c4 = (f & 15) * 4;
            *(float4*)&Bs[r][c4] = *(const float4*)&Xb[(long)(c0 + r) * HW + n0 + c4];
        }
        __syncthreads();
        #pragma unroll 8
        for (int kk = 0; kk < 32; ++kk) {
            float aa[5];
            #pragma unroll
            for (int i = 0; i < 5; ++i) aa[i] = As[kk][rt + 32 * i];
            float4 b0 = *(const float4*)&Bs[kk][ct * 8];
            float4 b1 = *(const float4*)&Bs[kk][ct * 8 + 4];
            float bb[8] = {b0.x, b0.y, b0.z, b0.w, b1.x, b1.y, b1.z, b1.w};
            #pragma unroll
            for (int i = 0; i < 5; ++i)
                #pragma unroll
                for (int j = 0; j < 8; ++j)
                    acc[i][j] = fmaf(aa[i], bb[j], acc[i][j]);
        }
        __syncthreads();
    }

    #pragma unroll
    for (int i = 0; i < 5; ++i)
        #pragma unroll
        for (int j = 0; j < 8; ++j)
            acc[i][j] = __expf(acc[i][j]);

    // store E rows < KCLS
    #pragma unroll
    for (int i = 0; i < 5; ++i) {
        int m = rt + 32 * i;
        if (m < KCLS) {
            long base = ((long)b * KCLS + m) * HW + n0 + ct * 8;
            *(float4*)&E[base]     = make_float4(acc[i][0], acc[i][1], acc[i][2], acc[i][3]);
            *(float4*)&E[base + 4] = make_float4(acc[i][4], acc[i][5], acc[i][6], acc[i][7]);
        }
    }

    // epilogue sums (reuse smem)
    float* S  = &As[0][0];   // 32x64 column partials
    float* Rd = &Bs[0][0];   // 160x8 row partials
    float cs[8] = {};
    #pragma unroll
    for (int i = 0; i < 5; ++i) {
        int m = rt + 32 * i;
        float rsum = 0.f;
        #pragma unroll
        for (int j = 0; j < 8; ++j) {
            float v = acc[i][j];
            rsum += v;
            if (m < KCLS) cs[j] += v;
        }
        Rd[m * 8 + ct] = rsum;
    }
    #pragma unroll
    for (int j = 0; j < 8; ++j) S[rt * 64 + ct * 8 + j] = cs[j];
    __syncthreads();
    if (t < 64) {
        float s = 0.f;
        for (int r = 0; r < 32; ++r) s += S[r * 64 + t];
        colinv[(long)b * HW + n0 + t] = 1.f / s;
    }
    if (t < KPAD) {
        float s = 0.f;
        #pragma unroll
        for (int c = 0; c < 8; ++c) s += Rd[t * 8 + c];
        rowpart[((long)b * KPAD + t) * 256 + blockIdx.x] = s;
    }
}

// ===========================================================================
__global__ void k_rowred(const float* __restrict__ rowpart, float* __restrict__ rinv)
{
    int idx = blockIdx.x * 256 + threadIdx.x;
    if (idx < BATCH * KPAD) {
        const float* p = rowpart + (long)idx * 256;
        float s = 0.f;
        for (int i = 0; i < 256; ++i) s += p[i];
        rinv[idx] = 1.f / s;
    }
}

// ===========================================================================
// clspool: poolpart[sp,b,k,c] = sum_{n in split} E[b,k,n] * x[b,c,n]
// Tile: BM=160(k) x BN=64(c), BK=32 over n.
// ===========================================================================
__global__ __launch_bounds__(256) void k_clspool(
    const float* __restrict__ E, const float* __restrict__ x,
    float* __restrict__ poolpart)
{
    __shared__ float As[32][161];   // [n][k]
    __shared__ float Bs[32][68];    // [n][c]  (padded rows, 16B aligned)
    const int t  = threadIdx.x;
    const int c0 = blockIdx.x * 64;
    const int sp = blockIdx.y;
    const int b  = blockIdx.z;
    const int rt = t >> 3, ct = t & 7;
    const float* Eb = E + (long)b * KCLS * HW;
    const float* Xb = x + (long)b * C * HW;
    const int nbase0 = sp * (HW / NSPLIT);

    float acc[5][8] = {};
    for (int nn = 0; nn < HW / NSPLIT; nn += 32) {
        const int nb = nbase0 + nn;
        #pragma unroll
        for (int i = 0; i < 5; ++i) {
            int f = t + 256 * i, row = f >> 3, c4 = (f & 7) * 4;
            float4 v = make_float4(0.f, 0.f, 0.f, 0.f);
            if (row < KCLS) v = *(const float4*)&Eb[(long)row * HW + nb + c4];
            As[c4 + 0][row] = v.x; As[c4 + 1][row] = v.y;
            As[c4 + 2][row] = v.z; As[c4 + 3][row] = v.w;
        }
        #pragma unroll
        for (int i = 0; i < 2; ++i) {
            int f = t + 256 * i, r = f >> 3, c4 = (f & 7) * 4;
            float4 v = *(const float4*)&Xb[(long)(c0 + r) * HW + nb + c4];
            Bs[c4 + 0][r] = v.x; Bs[c4 + 1][r] = v.y;
            Bs[c4 + 2][r] = v.z; Bs[c4 + 3][r] = v.w;
        }
        __syncthreads();
        #pragma unroll 8
        for (int kk = 0; kk < 32; ++kk) {
            float aa[5];
            #pragma unroll
            for (int i = 0; i < 5; ++i) aa[i] = As[kk][rt + 32 * i];
            float4 b0 = *(const float4*)&Bs[kk][ct * 8];
            float4 b1 = *(const float4*)&Bs[kk][ct * 8 + 4];
            float bb[8] = {b0.x, b0.y, b0.z, b0.w, b1.x, b1.y, b1.z, b1.w};
            #pragma unroll
            for (int i = 0; i < 5; ++i)
                #pragma unroll
                for (int j = 0; j < 8; ++j)
                    acc[i][j] = fmaf(aa[i], bb[j], acc[i][j]);
        }
        __syncthreads();
    }
    #pragma unroll
    for (int i = 0; i < 5; ++i) {
        int m = rt + 32 * i;
        long base = (((long)sp * BATCH + b) * KPAD + m) * C + c0 + ct * 8;
        *(float4*)&poolpart[base]     = make_float4(acc[i][0], acc[i][1], acc[i][2], acc[i][3]);
        *(float4*)&poolpart[base + 4] = make_float4(acc[i][4], acc[i][5], acc[i][6], acc[i][7]);
    }
}

// ===========================================================================
// Small linear: out[k,c] = sum_p A[k,p] * W[c,p]   (clsWf = cls @ Wfeat^T)
// ===========================================================================
__global__ __launch_bounds__(256) void k_clsWf(
    const float* __restrict__ A, const float* __restrict__ W,
    float* __restrict__ out)
{
    __shared__ float As[16][64];
    __shared__ float Bs[16][64];
    const int t = threadIdx.x;
    const int k0 = blockIdx.x * 64, c0 = blockIdx.y * 64;
    const int tm = (t >> 4) * 4, tn = (t & 15) * 4;
    const int arow = t >> 2, acol = (t & 3) * 4;
    const int bc = t >> 2, bp = (t & 3) * 4;
    float acc[4][4] = {};

    for (int p0 = 0; p0 < C; p0 += 16) {
        float4 av = make_float4(0.f, 0.f, 0.f, 0.f);
        if (k0 + arow < KCLS)
            av = *(const float4*)&A[(long)(k0 + arow) * C + p0 + acol];
        As[acol + 0][arow] = av.x; As[acol + 1][arow] = av.y;
        As[acol + 2][arow] = av.z; As[acol + 3][arow] = av.w;
        float4 bv = *(const float4*)&W[(long)(c0 + bc) * C + p0 + bp];
        Bs[bp + 0][bc] = bv.x; Bs[bp + 1][bc] = bv.y;
        Bs[bp + 2][bc] = bv.z; Bs[bp + 3][bc] = bv.w;
        __syncthreads();
        #pragma unroll
        for (int kk = 0; kk < 16; ++kk) {
            float4 a4 = *(const float4*)&As[kk][tm];
            float4 b4 = *(const float4*)&Bs[kk][tn];
            float aa[4] = {a4.x, a4.y, a4.z, a4.w};
            float bb[4] = {b4.x, b4.y, b4.z, b4.w};
            #pragma unroll
            for (int i = 0; i < 4; ++i)
                #pragma unroll
                for (int j = 0; j < 4; ++j)
                    acc[i][j] = fmaf(aa[i], bb[j], acc[i][j]);
        }
        __syncthreads();
    }
    #pragma unroll
    for (int i = 0; i < 4; ++i) {
        int k = k0 + tm + i;
        if (k < KCLS)
            *(float4*)&out[(long)k * C + c0 + tn] =
                make_float4(acc[i][0], acc[i][1], acc[i][2], acc[i][3]);
    }
}

// ===========================================================================
// acls[b,k,c] = cls[k,c] + rinv[b,k] * (sum_s poolpart) @ Wcls^T
// ===========================================================================
__global__ __launch_bounds__(256) void k_acls(
    const float* __restrict__ poolpart, const float* __restrict__ rinv,
    const float* __restrict__ W, const float* __restrict__ cls,
    float* __restrict__ out)
{
    __shared__ float As[16][64];
    __shared__ float Bs[16][64];
    const int t = threadIdx.x;
    const int k0 = blockIdx.x * 64, c0 = blockIdx.y * 64, b = blockIdx.z;
    const int tm = (t >> 4) * 4, tn = (t & 15) * 4;
    const int arow = t >> 2, acol = (t & 3) * 4;
    const int bc = t >> 2, bp = (t & 3) * 4;
    float acc[4][4] = {};
    const int ka = k0 + arow;
    const float rv = (ka < KCLS) ? rinv[b * KPAD + ka] : 0.f;

    for (int p0 = 0; p0 < C; p0 += 16) {
        float4 av = make_float4(0.f, 0.f, 0.f, 0.f);
        if (ka < KCLS) {
            #pragma unroll
            for (int s = 0; s < NSPLIT; ++s) {
                float4 v = *(const float4*)
                    &poolpart[(((long)s * BATCH + b) * KPAD + ka) * C + p0 + acol];
                av.x += v.x; av.y += v.y; av.z += v.z; av.w += v.w;
            }
            av.x *= rv; av.y *= rv; av.z *= rv; av.w *= rv;
        }
        As[acol + 0][arow] = av.x; As[acol + 1][arow] = av.y;
        As[acol + 2][arow] = av.z; As[acol + 3][arow] = av.w;
        float4 bv = *(const float4*)&W[(long)(c0 + bc) * C + p0 + bp];
        Bs[bp + 0][bc] = bv.x; Bs[bp + 1][bc] = bv.y;
        Bs[bp + 2][bc] = bv.z; Bs[bp + 3][bc] = bv.w;
        __syncthreads();
        #pragma unroll
        for (int kk = 0; kk < 16; ++kk) {
            float4 a4 = *(const float4*)&As[kk][tm];
            float4 b4 = *(const float4*)&Bs[kk][tn];
            float aa[4] = {a4.x, a4.y, a4.z, a4.w};
            float bb[4] = {b4.x, b4.y, b4.z, b4.w};
            #pragma unroll
            for (int i = 0; i < 4; ++i)
                #pragma unroll
                for (int j = 0; j < 4; ++j)
                    acc[i][j] = fmaf(aa[i], bb[j], acc[i][j]);
        }
        __syncthreads();
    }
    #pragma unroll
    for (int i = 0; i < 4; ++i) {
        int k = k0 + tm + i;
        if (k < KCLS) {
            #pragma unroll
            for (int j = 0; j < 4; ++j)
                out[((long)b * KCLS + k) * C + c0 + tn + j] =
                    acc[i][j] + cls[(long)k * C + c0 + tn + j];
        }
    }
}

// ===========================================================================
// G[b,k,k2] = sum_p acls[b,k,p] * clsWf[k2,p]    (zero-padded to 160x160)
// ===========================================================================
__global__ __launch_bounds__(256) void k_G(
    const float* __restrict__ acls, const float* __restrict__ clsWf,
    float* __restrict__ G)
{
    __shared__ float As[16][64];
    __shared__ float Bs[16][64];
    const int t = threadIdx.x;
    const int k0 = blockIdx.x * 64, k20 = blockIdx.y * 64, b = blockIdx.z;
    const int tm = (t >> 4) * 4, tn = (t & 15) * 4;
    const int arow = t >> 2, acol = (t & 3) * 4;
    const int bc = t >> 2, bp = (t & 3) * 4;
    float acc[4][4] = {};

    for (int p0 = 0; p0 < C; p0 += 16) {
        float4 av = make_float4(0.f, 0.f, 0.f, 0.f);
        if (k0 + arow < KCLS)
            av = *(const float4*)&acls[((long)b * KCLS + k0 + arow) * C + p0 + acol];
        As[acol + 0][arow] = av.x; As[acol + 1][arow] = av.y;
        As[acol + 2][arow] = av.z; As[acol + 3][arow] = av.w;
        float4 bv = make_float4(0.f, 0.f, 0.f, 0.f);
        if (k20 + bc < KCLS)
            bv = *(const float4*)&clsWf[(long)(k20 + bc) * C + p0 + bp];
        Bs[bp + 0][bc] = bv.x; Bs[bp + 1][bc] = bv.y;
        Bs[bp + 2][bc] = bv.z; Bs[bp + 3][bc] = bv.w;
        __syncthreads();
        #pragma unroll
        for (int kk = 0; kk < 16; ++kk) {
            float4 a4 = *(const float4*)&As[kk][tm];
            float4 b4 = *(const float4*)&Bs[kk][tn];
            float aa[4] = {a4.x, a4.y, a4.z, a4.w};
            float bb[4] = {b4.x, b4.y, b4.z, b4.w};
            #pragma unroll
            for (int i = 0; i < 4; ++i)
                #pragma unroll
                for (int j = 0; j < 4; ++j)
                    acc[i][j] = fmaf(aa[i], bb[j], acc[i][j]);
        }
        __syncthreads();
    }
    #pragma unroll
    for (int i = 0; i < 4; ++i) {
        int k = k0 + tm + i;
        if (k < KPAD && k20 + tn < KPAD)
            *(float4*)&G[((long)b * KPAD + k) * KPAD + k20 + tn] =
                make_float4(acc[i][0], acc[i][1], acc[i][2], acc[i][3]);
    }
}

// ===========================================================================
// masksLN: masks[k,n] = sum_c acls[k,c]*x[c,n] + sum_k' G[k,k']*(E[k',n]*colinv[n])
// then LayerNorm over k (150), write out [b,K,h,w].
// Tile: BM=160 (all k) x BN=64 (n).
// ===========================================================================
__global__ __launch_bounds__(256) void k_masksLN(
    const float* __restrict__ acls, const float* __restrict__ x,
    const float* __restrict__ G, const float* __restrict__ E,
    const float* __restrict__ colinv,
    const float* __restrict__ gamma, const float* __restrict__ beta,
    float* __restrict__ out)
{
    __shared__ float As[32][161];
    __shared__ float Bs[32][64];
    __shared__ float cinv_s[64], mean_s[64], rs_s[64];
    __shared__ float gam_s[KCLS], bet_s[KCLS];
    const int t  = threadIdx.x;
    const int n0 = blockIdx.x * 64;
    const int b  = blockIdx.y;
    const int rt = t >> 3, ct = t & 7;
    const float* Xb = x + (long)b * C * HW;

    if (t < 64) cinv_s[t] = colinv[(long)b * HW + n0 + t];
    if (t < KCLS) { gam_s[t] = gamma[t]; bet_s[t] = beta[t]; }
    __syncthreads();

    float acc[5][8] = {};

    // phase 1: reduction over c with A = acls, B = x
    for (int c0 = 0; c0 < C; c0 += 32) {
        #pragma unroll
        for (int i = 0; i < 5; ++i) {
            int f = t + 256 * i, row = f >> 3, c4 = (f & 7) * 4;
            float4 v = make_float4(0.f, 0.f, 0.f, 0.f);
            if (row < KCLS)
                v = *(const float4*)&acls[((long)b * KCLS + row) * C + c0 + c4];
            As[c4 + 0][row] = v.x; As[c4 + 1][row] = v.y;
            As[c4 + 2][row] = v.z; As[c4 + 3][row] = v.w;
        }
        #pragma unroll
        for (int i = 0; i < 2; ++i) {
            int f = t + 256 * i, r = f >> 4, c4 = (f & 15) * 4;
            *(float4*)&Bs[r][c4] = *(const float4*)&Xb[(long)(c0 + r) * HW + n0 + c4];
        }
        __syncthreads();
        #pragma unroll 8
        for (int kk = 0; kk < 32; ++kk) {
            float aa[5];
            #pragma unroll
            for (int i = 0; i < 5; ++i) aa[i] = As[kk][rt + 32 * i];
            float4 b0 = *(const float4*)&Bs[kk][ct * 8];
            float4 b1 = *(const float4*)&Bs[kk][ct * 8 + 4];
            float bb[8] = {b0.x, b0.y, b0.z, b0.w, b1.x, b1.y, b1.z, b1.w};
            #pragma unroll
            for (int i = 0; i < 5; ++i)
                #pragma unroll
                for (int j = 0; j < 8; ++j)
                    acc[i][j] = fmaf(aa[i], bb[j], acc[i][j]);
        }
        __syncthreads();
    }

    // phase 2: reduction over k' with A = G, B = E * colinv
    for (int kp0 = 0; kp0 < KPAD; kp0 += 32) {
        #pragma unroll
        for (int i = 0; i < 5; ++i) {
            int f = t + 256 * i, row = f >> 3, c4 = (f & 7) * 4;
            float4 v = *(const float4*)&G[((long)b * KPAD + row) * KPAD + kp0 + c4];
            As[c4 + 0][row] = v.x; As[c4 + 1][row] = v.y;
            As[c4 + 2][row] = v.z; As[c4 + 3][row] = v.w;
        }
        #pragma unroll
        for (int i = 0; i < 2; ++i) {
            int f = t + 256 * i, r = f >> 4, c4 = (f & 15) * 4;
            float4 v = make_float4(0.f, 0.f, 0.f, 0.f);
            if (kp0 + r < KCLS)
                v = *(const float4*)&E[((long)b * KCLS + kp0 + r) * HW + n0 + c4];
            v.x *= cinv_s[c4 + 0]; v.y *= cinv_s[c4 + 1];
            v.z *= cinv_s[c4 + 2]; v.w *= cinv_s[c4 + 3];
            *(float4*)&Bs[r][c4] = v;
        }
        __syncthreads();
        #pragma unroll 8
        for (int kk = 0; kk < 32; ++kk) {
            float aa[5];
            #pragma unroll
            for (int i = 0; i < 5; ++i) aa[i] = As[kk][rt + 32 * i];
            float4 b0 = *(const float4*)&Bs[kk][ct * 8];
            float4 b1 = *(const float4*)&Bs[kk][ct * 8 + 4];
            float bb[8] = {b0.x, b0.y, b0.z, b0.w, b1.x, b1.y, b1.z, b1.w};
            #pragma unroll
            for (int i = 0; i < 5; ++i)
                #pragma unroll
                for (int j = 0; j < 8; ++j)
                    acc[i][j] = fmaf(aa[i], bb[j], acc[i][j]);
        }
        __syncthreads();
    }

    // LayerNorm over k (150 valid rows) per column
    float* S1 = &As[0][0];
    float* S2 = &Bs[0][0];
    float ls[8] = {}, lq[8] = {};
    #pragma unroll
    for (int i = 0; i < 5; ++i) {
        int m = rt + 32 * i;
        if (m < KCLS) {
            #pragma unroll
            for (int j = 0; j < 8; ++j) {
                float v = acc[i][j];
                ls[j] += v; lq[j] += v * v;
            }
        }
    }
    #pragma unroll
    for (int j = 0; j < 8; ++j) {
        S1[rt * 64 + ct * 8 + j] = ls[j];
        S2[rt * 64 + ct * 8 + j] = lq[j];
    }
    __syncthreads();
    if (t < 64) {
        float s = 0.f, q = 0.f;
        for (int r = 0; r < 32; ++r) { s += S1[r * 64 + t]; q += S2[r * 64 + t]; }
        float mu  = s * (1.f / KCLS);
        float var = q * (1.f / KCLS) - mu * mu;
        mean_s[t] = mu;
        rs_s[t]   = rsqrtf(var + 1e-5f);
    }
    __syncthreads();
    #pragma unroll
    for (int i = 0; i < 5; ++i) {
        int m = rt + 32 * i;
        if (m < KCLS) {
            float g = gam_s[m], be = bet_s[m];
            float o[8];
            #pragma unroll
            for (int j = 0; j < 8; ++j) {
                int col = ct * 8 + j;
                o[j] = (acc[i][j] - mean_s[col]) * rs_s[col] * g + be;
            }
            long base = ((long)b * KCLS + m) * HW + n0 + ct * 8;
            *(float4*)&out[base]     = make_float4(o[0], o[1], o[2], o[3]);
            *(float4*)&out[base + 4] = make_float4(o[4], o[5], o[6], o[7]);
        }
    }
}

// ===========================================================================
extern "C" void kernel_launch(void* const* d_in, const int* in_sizes, int n_in,
                              void* d_out, int out_size)
{
    const float* x     = (const float*)d_in[0];
    const float* cls   = (const float*)d_in[1];
    const float* Wcls  = (const float*)d_in[2];
    const float* Wfeat = (const float*)d_in[3];
    const float* gamma = (const float*)d_in[4];
    const float* beta  = (const float*)d_in[5];
    float* out = (float*)d_out;

    float *E, *colinv, *rowpart, *rinv, *poolpart, *acls, *clsWf, *G;
    cudaGetSymbolAddress((void**)&E,        g_E);
    cudaGetSymbolAddress((void**)&colinv,   g_colinv);
    cudaGetSymbolAddress((void**)&rowpart,  g_rowpart);
    cudaGetSymbolAddress((void**)&rinv,     g_rinv);
    cudaGetSymbolAddress((void**)&poolpart, g_poolpart);
    cudaGetSymbolAddress((void**)&acls,     g_acls);
    cudaGetSymbolAddress((void**)&clsWf,    g_clsWf);
    cudaGetSymbolAddress((void**)&G,        g_G);

    // 1. E = exp(cls @ x), colinv, row partials
    k_gemm1<<<dim3(HW / 64, BATCH), 256>>>(cls, x, E, colinv, rowpart);
    // 2. row-sum reduce -> rinv
    k_rowred<<<(BATCH * KPAD + 255) / 256, 256>>>(rowpart, rinv);
    // 3. pooling partials
    k_clspool<<<dim3(C / 64, NSPLIT, BATCH), 256>>>(E, x, poolpart);
    // 4. clsWf = cls @ Wfeat^T
    k_clsWf<<<dim3(3, C / 64), 256>>>(cls, Wfeat, clsWf);
    // 5. acls = cls + rinv * (sum poolpart) @ Wcls^T
    k_acls<<<dim3(3, C / 64, BATCH), 256>>>(poolpart, rinv, Wcls, cls, acls);
    // 6. G = acls @ clsWf^T (padded 160x160)
    k_G<<<dim3(3, 3, BATCH), 256>>>(acls, clsWf, G);
    // 7. masks + LayerNorm + output
    k_masksLN<<<dim3(HW / 64, BATCH), 256>>>(acls, x, G, E, colinv, gamma, beta, out);
}

// round 5
// speedup vs baseline: 1.6001x; 1.6001x over previous
#include <cuda_runtime.h>
#include <stdint.h>

#define BATCH 8
#define C 512
#define HW 16384
#define KCLS 150
#define KPAD 160
#define KP2 192
#define NSPLIT 16
#define KC 32
#define LDT 17   // u32 row stride of smem tiles

typedef unsigned int u32;
typedef unsigned short u16;

// ---------------- scratch (device globals; no allocations) ----------------
__device__ u16  g_clsh[KPAD * C];
__device__ u16  g_clsl[KPAD * C];
__device__ u32  g_E32[(long)BATCH * KCLS * HW];  // packed: hi bf16 (low16) | lo bf16 (high16)
__device__ float g_colinv[BATCH * HW];
__device__ float g_rinv[BATCH * KPAD];
__device__ float g_poolpart[(long)NSPLIT * BATCH * KCLS * C];
__device__ float g_acls[BATCH * KCLS * C];
__device__ u16  g_aclsh[BATCH * KPAD * C];
__device__ u16  g_aclsl[BATCH * KPAD * C];
__device__ float g_clsWf[KCLS * C];
__device__ u16  g_Gh[BATCH * KPAD * KP2];
__device__ u16  g_Gl[BATCH * KPAD * KP2];

// ---------------- helpers ----------------
__device__ __forceinline__ void split2(float v0, float v1, u32* hv, u32* lv) {
    u32 u0 = __float_as_uint(v0), u1 = __float_as_uint(v1);
    float l0 = v0 - __uint_as_float(u0 & 0xFFFF0000u);
    float l1 = v1 - __uint_as_float(u1 & 0xFFFF0000u);
    *hv = __byte_perm(u0, u1, 0x7632);
    *lv = __byte_perm(__float_as_uint(l0), __float_as_uint(l1), 0x7632);
}
__device__ __forceinline__ u32 packE(float e) {
    u32 u = __float_as_uint(e);
    float lo = e - __uint_as_float(u & 0xFFFF0000u);
    return (u >> 16) | (__float_as_uint(lo) & 0xFFFF0000u);
}
__device__ __forceinline__ float unpackE(u32 w) {
    return __uint_as_float((w & 0xFFFFu) << 16) + __uint_as_float(w & 0xFFFF0000u);
}
__device__ __forceinline__ void mma16816(float c[4], const u32 a[4], const u32 b[2]) {
    asm volatile(
        "mma.sync.aligned.m16n8k16.row.col.f32.bf16.bf16.f32 "
        "{%0,%1,%2,%3}, {%4,%5,%6,%7}, {%8,%9}, {%0,%1,%2,%3};"
        : "+f"(c[0]), "+f"(c[1]), "+f"(c[2]), "+f"(c[3])
        : "r"(a[0]), "r"(a[1]), "r"(a[2]), "r"(a[3]), "r"(b[0]), "r"(b[1]));
}

// Compute the 128x160 CTA tile's contribution for one K-chunk of 32.
// Warp (wm,wn) owns rows [wm*64, +64), cols [wn*40, +40).
__device__ __forceinline__ void tile_mma(
    const u32* __restrict__ Ah, const u32* __restrict__ Al,
    const u32* __restrict__ Bh, const u32* __restrict__ Bl,
    float (*acc)[5][4], int wm, int wn, int g, int tid)
{
    #pragma unroll
    for (int ks = 0; ks < 2; ++ks) {
        const int k2b = ks * 8;
        u32 ah[4][4], al[4][4];
        #pragma unroll
        for (int mi = 0; mi < 4; ++mi) {
            const int r = wm * 64 + mi * 16 + g;
            const u32* ph = Ah + r * LDT + k2b + tid;
            const u32* pl = Al + r * LDT + k2b + tid;
            ah[mi][0] = ph[0]; ah[mi][1] = ph[8 * LDT];
            ah[mi][2] = ph[4]; ah[mi][3] = ph[8 * LDT + 4];
            al[mi][0] = pl[0]; al[mi][1] = pl[8 * LDT];
            al[mi][2] = pl[4]; al[mi][3] = pl[8 * LDT + 4];
        }
        #pragma unroll
        for (int ni = 0; ni < 5; ++ni) {
            const int nn = wn * 40 + ni * 8 + g;
            const u32* qh = Bh + nn * LDT + k2b + tid;
            const u32* ql = Bl + nn * LDT + k2b + tid;
            u32 bh[2] = {qh[0], qh[4]};
            u32 bl[2] = {ql[0], ql[4]};
            #pragma unroll
            for (int mi = 0; mi < 4; ++mi) {
                mma16816(acc[mi][ni], ah[mi], bh);
                mma16816(acc[mi][ni], al[mi], bh);
                mma16816(acc[mi][ni], ah[mi], bl);
            }
        }
    }
}

// Fill B tile (KPAD rows x 16 u32) from u16 hi/lo arrays.
__device__ __forceinline__ void fill_B(
    u32* Bh, u32* Bl, const u16* bh, const u16* bl,
    int stride32, int cb2, int rows_valid, int t)
{
    for (int i = t; i < KPAD * 16; i += 256) {
        int k = i >> 4, c2 = i & 15;
        u32 hv = 0, lv = 0;
        if (k < rows_valid) {
            hv = ((const u32*)bh)[k * stride32 + cb2 + c2];
            lv = ((const u32*)bl)[k * stride32 + cb2 + c2];
        }
        Bh[k * LDT + c2] = hv;
        Bl[k * LDT + c2] = lv;
    }
}

// ===========================================================================
// GEMM1 (HMMA): D[n=128, k=160] = x^T · cls ; E=exp(D) packed, colinv.
// ===========================================================================
__global__ __launch_bounds__(256) void k_gemm1_mma(
    const float* __restrict__ x, const u16* __restrict__ clsh, const u16* __restrict__ clsl,
    u32* __restrict__ E32, float* __restrict__ colinv)
{
    __shared__ u32 sAh[128 * LDT], sAl[128 * LDT], sBh[KPAD * LDT], sBl[KPAD * LDT];
    __shared__ float srow[128];
    const int t = threadIdx.x;
    const int wid = t >> 5, lane = t & 31, g = lane >> 2, tid = lane & 3;
    const int wm = wid >> 2, wn = wid & 3;
    const int n0 = blockIdx.x * 128, b = blockIdx.y;
    if (t < 128) srow[t] = 0.f;

    float acc[4][5][4] = {};
    const int n = t & 127, half = t >> 7;
    const float* xb = x + (long)b * C * HW + n0 + n;

    for (int cc = 0; cc < C / KC; ++cc) {
        #pragma unroll
        for (int j = 0; j < 8; ++j) {
            int c2 = half * 8 + j;
            int c = cc * KC + c2 * 2;
            u32 hv, lv;
            split2(xb[(long)c * HW], xb[(long)(c + 1) * HW], &hv, &lv);
            sAh[n * LDT + c2] = hv;
            sAl[n * LDT + c2] = lv;
        }
        fill_B(sBh, sBl, clsh, clsl, C / 2, cc * 16, KPAD, t);
        __syncthreads();
        tile_mma(sAh, sAl, sBh, sBl, acc, wm, wn, g, tid);
        __syncthreads();
    }

    #pragma unroll
    for (int mi = 0; mi < 4; ++mi) {
        const int r0 = wm * 64 + mi * 16 + g;
        float s0 = 0.f, s1 = 0.f;
        #pragma unroll
        for (int ni = 0; ni < 5; ++ni) {
            const int cb = wn * 40 + ni * 8 + tid * 2;
            float e0 = __expf(acc[mi][ni][0]);
            float e1 = __expf(acc[mi][ni][1]);
            float e2 = __expf(acc[mi][ni][2]);
            float e3 = __expf(acc[mi][ni][3]);
            if (cb < KCLS) {
                E32[((long)b * KCLS + cb) * HW + n0 + r0]     = packE(e0);
                E32[((long)b * KCLS + cb) * HW + n0 + r0 + 8] = packE(e2);
                s0 += e0; s1 += e2;
            }
            if (cb + 1 < KCLS) {
                E32[((long)b * KCLS + cb + 1) * HW + n0 + r0]     = packE(e1);
                E32[((long)b * KCLS + cb + 1) * HW + n0 + r0 + 8] = packE(e3);
                s0 += e1; s1 += e3;
            }
        }
        atomicAdd(&srow[r0], s0);
        atomicAdd(&srow[r0 + 8], s1);
    }
    __syncthreads();
    if (t < 128) colinv[(long)b * HW + n0 + t] = 1.f / srow[t];
}

// ===========================================================================
// pool (HMMA): D[c=128, k=160] = sum_n x[c,n] * E[k,n]  (split-K over n)
// ===========================================================================
__global__ __launch_bounds__(256) void k_pool_mma(
    const float* __restrict__ x, const u32* __restrict__ E32, float* __restrict__ poolpart)
{
    __shared__ u32 sAh[128 * LDT], sAl[128 * LDT], sBh[KPAD * LDT], sBl[KPAD * LDT];
    const int t = threadIdx.x;
    const int wid = t >> 5, lane = t & 31, g = lane >> 2, tid = lane & 3;
    const int wm = wid >> 2, wn = wid & 3;
    const int c0 = blockIdx.x * 128, sp = blockIdx.y, b = blockIdx.z;
    const int nbase = sp * (HW / NSPLIT);
    float acc[4][5][4] = {};

    for (int nn = 0; nn < HW / NSPLIT; nn += KC) {
        const int nb = nbase + nn;
        for (int i = t; i < 128 * 16; i += 256) {
            int r = i >> 4, c2 = i & 15;
            float2 v = *(const float2*)(x + ((long)b * C + c0 + r) * HW + nb + c2 * 2);
            u32 hv, lv;
            split2(v.x, v.y, &hv, &lv);
            sAh[r * LDT + c2] = hv;
            sAl[r * LDT + c2] = lv;
        }
        for (int i = t; i < KPAD * 16; i += 256) {
            int k = i >> 4, c2 = i & 15;
            u32 hv = 0, lv = 0;
            if (k < KCLS) {
                const u32* p = E32 + ((long)b * KCLS + k) * HW + nb + c2 * 2;
                u32 a = p[0], bb = p[1];
                hv = __byte_perm(a, bb, 0x5410);
                lv = __byte_perm(a, bb, 0x7632);
            }
            sBh[k * LDT + c2] = hv;
            sBl[k * LDT + c2] = lv;
        }
        __syncthreads();
        tile_mma(sAh, sAl, sBh, sBl, acc, wm, wn, g, tid);
        __syncthreads();
    }

    const long base = ((long)sp * BATCH + b) * KCLS;
    #pragma unroll
    for (int mi = 0; mi < 4; ++mi) {
        const int r0 = wm * 64 + mi * 16 + g;
        #pragma unroll
        for (int ni = 0; ni < 5; ++ni) {
            const int cb = wn * 40 + ni * 8 + tid * 2;
            if (cb < KCLS) {
                poolpart[(base + cb) * C + c0 + r0]     = acc[mi][ni][0];
                poolpart[(base + cb) * C + c0 + r0 + 8] = acc[mi][ni][2];
            }
            if (cb + 1 < KCLS) {
                poolpart[(base + cb + 1) * C + c0 + r0]     = acc[mi][ni][1];
                poolpart[(base + cb + 1) * C + c0 + r0 + 8] = acc[mi][ni][3];
            }
        }
    }
}

// ===========================================================================
// masks (HMMA): D[n=128,k=160] = x^T·acls + pos_attn·G^T, then LayerNorm.
// ===========================================================================
__global__ __launch_bounds__(256) void k_masks_mma(
    const float* __restrict__ x, const u16* __restrict__ aclsh, const u16* __restrict__ aclsl,
    const u16* __restrict__ Gh, const u16* __restrict__ Gl,
    const u32* __restrict__ E32, const float* __restrict__ colinv,
    const float* __restrict__ gamma, const float* __restrict__ beta,
    float* __restrict__ out)
{
    __shared__ u32 sAh[128 * LDT], sAl[128 * LDT], sBh[KPAD * LDT], sBl[KPAD * LDT];
    __shared__ float ssum[128], ssq[128], civ[128], gam[KCLS], bet[KCLS];
    const int t = threadIdx.x;
    const int wid = t >> 5, lane = t & 31, g = lane >> 2, tid = lane & 3;
    const int wm = wid >> 2, wn = wid & 3;
    const int n0 = blockIdx.x * 128, b = blockIdx.y;
    if (t < 128) {
        ssum[t] = 0.f; ssq[t] = 0.f;
        civ[t] = colinv[(long)b * HW + n0 + t];
    }
    for (int i = t; i < KCLS; i += 256) { gam[i] = gamma[i]; bet[i] = beta[i]; }

    float acc[4][5][4] = {};
    const int n = t & 127, half = t >> 7;
    const float* xb = x + (long)b * C * HW + n0 + n;

    // phase 1: reduction over c  (A = x^T, B = acls)
    for (int cc = 0; cc < C / KC; ++cc) {
        #pragma unroll
        for (int j = 0; j < 8; ++j) {
            int c2 = half * 8 + j;
            int c = cc * KC + c2 * 2;
            u32 hv, lv;
            split2(xb[(long)c * HW], xb[(long)(c + 1) * HW], &hv, &lv);
            sAh[n * LDT + c2] = hv;
            sAl[n * LDT + c2] = lv;
        }
        fill_B(sBh, sBl, aclsh + (long)b * KPAD * C, aclsl + (long)b * KPAD * C,
               C / 2, cc * 16, KCLS, t);
        __syncthreads();
        tile_mma(sAh, sAl, sBh, sBl, acc, wm, wn, g, tid);
        __syncthreads();
    }
    // phase 2: reduction over k'  (A = pos_attn, B = G)
    __syncthreads();
    const float ci = civ[n];
    for (int pc = 0; pc < KP2 / KC; ++pc) {
        #pragma unroll
        for (int j = 0; j < 8; ++j) {
            int q2 = half * 8 + j;
            int kq = pc * KC + q2 * 2;
            float v0 = 0.f, v1 = 0.f;
            if (kq < KCLS)
                v0 = unpackE(E32[((long)b * KCLS + kq) * HW + n0 + n]) * ci;
            if (kq + 1 < KCLS)
                v1 = unpackE(E32[((long)b * KCLS + kq + 1) * HW + n0 + n]) * ci;
            u32 hv, lv;
            split2(v0, v1, &hv, &lv);
            sAh[n * LDT + q2] = hv;
            sAl[n * LDT + q2] = lv;
        }
        fill_B(sBh, sBl, Gh + (long)b * KPAD * KP2, Gl + (long)b * KPAD * KP2,
               KP2 / 2, pc * 16, KPAD, t);
        __syncthreads();
        tile_mma(sAh, sAl, sBh, sBl, acc, wm, wn, g, tid);
        __syncthreads();
    }

    // LayerNorm stats over k (<150) via smem atomics
    #pragma unroll
    for (int mi = 0; mi < 4; ++mi) {
        const int r0 = wm * 64 + mi * 16 + g;
        float s0 = 0.f, q0 = 0.f, s1 = 0.f, q1 = 0.f;
        #pragma unroll
        for (int ni = 0; ni < 5; ++ni) {
            const int cb = wn * 40 + ni * 8 + tid * 2;
            if (cb < KCLS) {
                float v = acc[mi][ni][0]; s0 += v; q0 += v * v;
                v = acc[mi][ni][2]; s1 += v; q1 += v * v;
            }
            if (cb + 1 < KCLS) {
                float v = acc[mi][ni][1]; s0 += v; q0 += v * v;
                v = acc[mi][ni][3]; s1 += v; q1 += v * v;
            }
        }
        atomicAdd(&ssum[r0], s0); atomicAdd(&ssq[r0], q0);
        atomicAdd(&ssum[r0 + 8], s1); atomicAdd(&ssq[r0 + 8], q1);
    }
    __syncthreads();
    #pragma unroll
    for (int mi = 0; mi < 4; ++mi) {
        const int r0 = wm * 64 + mi * 16 + g;
        const float mu0 = ssum[r0] * (1.f / KCLS);
        const float rs0 = rsqrtf(ssq[r0] * (1.f / KCLS) - mu0 * mu0 + 1e-5f);
        const float mu1 = ssum[r0 + 8] * (1.f / KCLS);
        const float rs1 = rsqrtf(ssq[r0 + 8] * (1.f / KCLS) - mu1 * mu1 + 1e-5f);
        #pragma unroll
        for (int ni = 0; ni < 5; ++ni) {
            const int cb = wn * 40 + ni * 8 + tid * 2;
            if (cb < KCLS) {
                out[((long)b * KCLS + cb) * HW + n0 + r0] =
                    (acc[mi][ni][0] - mu0) * rs0 * gam[cb] + bet[cb];
                out[((long)b * KCLS + cb) * HW + n0 + r0 + 8] =
                    (acc[mi][ni][2] - mu1) * rs1 * gam[cb] + bet[cb];
            }
            if (cb + 1 < KCLS) {
                out[((long)b * KCLS + cb + 1) * HW + n0 + r0] =
                    (acc[mi][ni][1] - mu0) * rs0 * gam[cb + 1] + bet[cb + 1];
                out[((long)b * KCLS + cb + 1) * HW + n0 + r0 + 8] =
                    (acc[mi][ni][3] - mu1) * rs1 * gam[cb + 1] + bet[cb + 1];
            }
        }
    }
}

// ===========================================================================
// SIMT small kernels
// ===========================================================================
__global__ void k_prep(const float* __restrict__ cls, u16* __restrict__ ch_, u16* __restrict__ cl_)
{
    int i = blockIdx.x * 256 + threadIdx.x;
    if (i < KPAD * C) {
        float v = (i < KCLS * C) ? cls[i] : 0.f;
        u32 u = __float_as_uint(v);
        float l = v - __uint_as_float(u & 0xFFFF0000u);
        ch_[i] = (u16)(u >> 16);
        cl_[i] = (u16)(__float_as_uint(l) >> 16);
    }
}

__global__ __launch_bounds__(256) void k_rowred(const u32* __restrict__ E32, float* __restrict__ rinv)
{
    const int k = blockIdx.x, b = blockIdx.y, t = threadIdx.x;
    const u32* p = E32 + ((long)b * KCLS + k) * HW;
    __shared__ float red[256];
    float s = 0.f;
    for (int i = t; i < HW; i += 256) s += unpackE(p[i]);
    red[t] = s; __syncthreads();
    for (int st = 128; st > 0; st >>= 1) {
        if (t < st) red[t] += red[t + st];
        __syncthreads();
    }
    if (t == 0) rinv[b * KPAD + k] = 1.f / red[0];
}

__device__ __forceinline__ void sg_body(
    const float* __restrict__ A, int arow_valid, const float* __restrict__ W, int brow_valid,
    float acc[4][4], int t, float As[16][64], float Bs[16][64])
{
    const int tm = (t >> 4) * 4, tn = (t & 15) * 4;
    const int ar = t >> 2, ac = (t & 3) * 4;
    const int bc = t >> 2, bp = (t & 3) * 4;
    for (int p0 = 0; p0 < C; p0 += 16) {
        float4 av = make_float4(0.f, 0.f, 0.f, 0.f);
        if (ar < arow_valid) av = *(const float4*)&A[(long)ar * C + p0 + ac];
        As[ac + 0][ar] = av.x; As[ac + 1][ar] = av.y; As[ac + 2][ar] = av.z; As[ac + 3][ar] = av.w;
        float4 bv = make_float4(0.f, 0.f, 0.f, 0.f);
        if (bc < brow_valid) bv = *(const float4*)&W[(long)bc * C + p0 + bp];
        Bs[bp + 0][bc] = bv.x; Bs[bp + 1][bc] = bv.y; Bs[bp + 2][bc] = bv.z; Bs[bp + 3][bc] = bv.w;
        __syncthreads();
        #pragma unroll
        for (int kk = 0; kk < 16; ++kk) {
            float4 a4 = *(const float4*)&As[kk][tm];
            float4 b4 = *(const float4*)&Bs[kk][tn];
            float aa[4] = {a4.x, a4.y, a4.z, a4.w};
            float bb[4] = {b4.x, b4.y, b4.z, b4.w};
            #pragma unroll
            for (int i = 0; i < 4; ++i)
                #pragma unroll
                for (int j = 0; j < 4; ++j)
                    acc[i][j] = fmaf(aa[i], bb[j], acc[i][j]);
        }
        __syncthreads();
    }
}

__global__ __launch_bounds__(256) void k_clsWf(
    const float* __restrict__ cls, const float* __restrict__ W, float* __restrict__ outw)
{
    __shared__ float As[16][64], Bs[16][64];
    const int t = threadIdx.x, k0 = blockIdx.x * 64, c0 = blockIdx.y * 64;
    float acc[4][4] = {};
    int av = KCLS - k0; av = av > 64 ? 64 : (av > 0 ? av : 0);
    sg_body(cls + (long)k0 * C, av, W + (long)c0 * C, 64, acc, t, As, Bs);
    const int tm = (t >> 4) * 4, tn = (t & 15) * 4;
    #pragma unroll
    for (int i = 0; i < 4; ++i) {
        int k = k0 + tm + i;
        if (k < KCLS)
            *(float4*)&outw[(long)k * C + c0 + tn] =
                make_float4(acc[i][0], acc[i][1], acc[i][2], acc[i][3]);
    }
}

__global__ __launch_bounds__(256) void k_acls(
    const float* __restrict__ poolpart, const float* __restrict__ rinv,
    const float* __restrict__ W, const float* __restrict__ cls,
    float* __restrict__ outf, u16* __restrict__ outh, u16* __restrict__ outl)
{
    __shared__ float As[16][64], Bs[16][64];
    const int t = threadIdx.x;
    const int k0 = blockIdx.x * 64, c0 = blockIdx.y * 64, b = blockIdx.z;
    const int tm = (t >> 4) * 4, tn = (t & 15) * 4;
    const int ar = t >> 2, ac = (t & 3) * 4;
    const int bc = t >> 2, bp = (t & 3) * 4;
    float acc[4][4] = {};
    const int ka = k0 + ar;
    const float rv = (ka < KCLS) ? rinv[b * KPAD + ka] : 0.f;

    for (int p0 = 0; p0 < C; p0 += 16) {
        float4 av = make_float4(0.f, 0.f, 0.f, 0.f);
        if (ka < KCLS) {
            #pragma unroll
            for (int s = 0; s < NSPLIT; ++s) {
                float4 v = *(const float4*)
                    &poolpart[(((long)s * BATCH + b) * KCLS + ka) * C + p0 + ac];
                av.x += v.x; av.y += v.y; av.z += v.z; av.w += v.w;
            }
            av.x *= rv; av.y *= rv; av.z *= rv; av.w *= rv;
        }
        As[ac + 0][ar] = av.x; As[ac + 1][ar] = av.y; As[ac + 2][ar] = av.z; As[ac + 3][ar] = av.w;
        float4 bv = *(const float4*)&W[(long)(c0 + bc) * C + p0 + bp];
        Bs[bp + 0][bc] = bv.x; Bs[bp + 1][bc] = bv.y; Bs[bp + 2][bc] = bv.z; Bs[bp + 3][bc] = bv.w;
        __syncthreads();
        #pragma unroll
        for (int kk = 0; kk < 16; ++kk) {
            float4 a4 = *(const float4*)&As[kk][tm];
            float4 b4 = *(const float4*)&Bs[kk][tn];
            float aa[4] = {a4.x, a4.y, a4.z, a4.w};
            float bb[4] = {b4.x, b4.y, b4.z, b4.w};
            #pragma unroll
            for (int i = 0; i < 4; ++i)
                #pragma unroll
                for (int j = 0; j < 4; ++j)
                    acc[i][j] = fmaf(aa[i], bb[j], acc[i][j]);
        }
        __syncthreads();
    }
    #pragma unroll
    for (int i = 0; i < 4; ++i) {
        int k = k0 + tm + i;
        if (k < KCLS) {
            #pragma unroll
            for (int j = 0; j < 4; ++j) {
                float v = acc[i][j] + cls[(long)k * C + c0 + tn + j];
                outf[((long)b * KCLS + k) * C + c0 + tn + j] = v;
                long po = ((long)b * KPAD + k) * C + c0 + tn + j;
                u32 u = __float_as_uint(v);
                float l = v - __uint_as_float(u & 0xFFFF0000u);
                outh[po] = (u16)(u >> 16);
                outl[po] = (u16)(__float_as_uint(l) >> 16);
            }
        }
    }
}

__global__ __launch_bounds__(256) void k_G(
    const float* __restrict__ acls, const float* __restrict__ clsWf,
    u16* __restrict__ Gh, u16* __restrict__ Gl)
{
    __shared__ float As[16][64], Bs[16][64];
    const int t = threadIdx.x;
    const int k0 = blockIdx.x * 64, k20 = blockIdx.y * 64, b = blockIdx.z;
    float acc[4][4] = {};
    int av = KCLS - k0; av = av > 64 ? 64 : (av > 0 ? av : 0);
    int bv = KCLS - k20; bv = bv > 64 ? 64 : (bv > 0 ? bv : 0);
    sg_body(acls + ((long)b * KCLS + k0) * C, av, clsWf + (long)k20 * C, bv, acc, t, As, Bs);
    const int tm = (t >> 4) * 4, tn = (t & 15) * 4;
    #pragma unroll
    for (int i = 0; i < 4; ++i) {
        int k = k0 + tm + i;
        if (k < KPAD) {
            #pragma unroll
            for (int j = 0; j < 4; ++j) {
                float v = acc[i][j];
                long po = ((long)b * KPAD + k) * KP2 + k20 + tn + j;
                u32 u = __float_as_uint(v);
                float l = v - __uint_as_float(u & 0xFFFF0000u);
                Gh[po] = (u16)(u >> 16);
                Gl[po] = (u16)(__float_as_uint(l) >> 16);
            }
        }
    }
}

// ===========================================================================
extern "C" void kernel_launch(void* const* d_in, const int* in_sizes, int n_in,
                              void* d_out, int out_size)
{
    const float* x     = (const float*)d_in[0];
    const float* cls   = (const float*)d_in[1];
    const float* Wcls  = (const float*)d_in[2];
    const float* Wfeat = (const float*)d_in[3];
    const float* gamma = (const float*)d_in[4];
    const float* beta  = (const float*)d_in[5];
    float* out = (float*)d_out;

    u16 *clsh, *clsl, *aclsh, *aclsl, *Gh, *Gl;
    u32* E32;
    float *colinv, *rinv, *poolpart, *acls, *clsWf;
    cudaGetSymbolAddress((void**)&clsh,  g_clsh);
    cudaGetSymbolAddress((void**)&clsl,  g_clsl);
    cudaGetSymbolAddress((void**)&E32,   g_E32);
    cudaGetSymbolAddress((void**)&colinv, g_colinv);
    cudaGetSymbolAddress((void**)&rinv,  g_rinv);
    cudaGetSymbolAddress((void**)&poolpart, g_poolpart);
    cudaGetSymbolAddress((void**)&acls,  g_acls);
    cudaGetSymbolAddress((void**)&aclsh, g_aclsh);
    cudaGetSymbolAddress((void**)&aclsl, g_aclsl);
    cudaGetSymbolAddress((void**)&clsWf, g_clsWf);
    cudaGetSymbolAddress((void**)&Gh,    g_Gh);
    cudaGetSymbolAddress((void**)&Gl,    g_Gl);

    k_prep<<<(KPAD * C + 255) / 256, 256>>>(cls, clsh, clsl);
    k_gemm1_mma<<<dim3(HW / 128, BATCH), 256>>>(x, clsh, clsl, E32, colinv);
    k_rowred<<<dim3(KCLS, BATCH), 256>>>(E32, rinv);
    k_pool_mma<<<dim3(C / 128, NSPLIT, BATCH), 256>>>(x, E32, poolpart);
    k_clsWf<<<dim3(3, C / 64), 256>>>(cls, Wfeat, clsWf);
    k_acls<<<dim3(3, C / 64, BATCH), 256>>>(poolpart, rinv, Wcls, cls, acls, aclsh, aclsl);
    k_G<<<dim3(3, 3, BATCH), 256>>>(acls, clsWf, Gh, Gl);
    k_masks_mma<<<dim3(HW / 128, BATCH), 256>>>(
        x, aclsh, aclsl, Gh, Gl, E32, colinv, gamma, beta, out);
}

// round 6
// speedup vs baseline: 2.4169x; 1.5104x over previous
#include <cuda_runtime.h>
#include <stdint.h>

#define BATCH 8
#define C 512
#define HW 16384
#define KCLS 150
#define KPAD 160
#define KP2 192
#define NSPLIT 16
#define KC 32
#define LDT 17   // u32 row stride of smem tiles

typedef unsigned int u32;
typedef unsigned short u16;

// ---------------- scratch (device globals; no allocations) ----------------
__device__ u16  g_clsh[KPAD * C];
__device__ u16  g_clsl[KPAD * C];
__device__ u32  g_E32[(long)BATCH * KCLS * HW];  // packed: hi bf16 (low16) | lo bf16 (high16)
__device__ float g_colinv[BATCH * HW];
__device__ float g_rowpart[(long)BATCH * KPAD * (HW / 128)];
__device__ float g_rinv[BATCH * KPAD];
__device__ float g_poolpart[(long)NSPLIT * BATCH * KCLS * C];
__device__ float g_acls[BATCH * KCLS * C];
__device__ u16  g_aclsh[BATCH * KPAD * C];
__device__ u16  g_aclsl[BATCH * KPAD * C];
__device__ float g_clsWf[KCLS * C];
__device__ u16  g_Gh[BATCH * KPAD * KP2];
__device__ u16  g_Gl[BATCH * KPAD * KP2];

// ---------------- helpers ----------------
__device__ __forceinline__ void split2(float v0, float v1, u32* hv, u32* lv) {
    u32 u0 = __float_as_uint(v0), u1 = __float_as_uint(v1);
    float l0 = v0 - __uint_as_float(u0 & 0xFFFF0000u);
    float l1 = v1 - __uint_as_float(u1 & 0xFFFF0000u);
    *hv = __byte_perm(u0, u1, 0x7632);
    *lv = __byte_perm(__float_as_uint(l0), __float_as_uint(l1), 0x7632);
}
__device__ __forceinline__ u32 packE(float e) {
    u32 u = __float_as_uint(e);
    float lo = e - __uint_as_float(u & 0xFFFF0000u);
    return (u >> 16) | (__float_as_uint(lo) & 0xFFFF0000u);
}
__device__ __forceinline__ float unpackE(u32 w) {
    return __uint_as_float((w & 0xFFFFu) << 16) + __uint_as_float(w & 0xFFFF0000u);
}
__device__ __forceinline__ void mma16816(float c[4], const u32 a[4], const u32 b[2]) {
    asm volatile(
        "mma.sync.aligned.m16n8k16.row.col.f32.bf16.bf16.f32 "
        "{%0,%1,%2,%3}, {%4,%5,%6,%7}, {%8,%9}, {%0,%1,%2,%3};"
        : "+f"(c[0]), "+f"(c[1]), "+f"(c[2]), "+f"(c[3])
        : "r"(a[0]), "r"(a[1]), "r"(a[2]), "r"(a[3]), "r"(b[0]), "r"(b[1]));
}

// Compute the 128x160 CTA tile's contribution for one K-chunk of 32.
// Warp (wm,wn) owns rows [wm*64, +64), cols [wn*40, +40).
__device__ __forceinline__ void tile_mma(
    const u32* __restrict__ Ah, const u32* __restrict__ Al,
    const u32* __restrict__ Bh, const u32* __restrict__ Bl,
    float (*acc)[5][4], int wm, int wn, int g, int tid)
{
    #pragma unroll
    for (int ks = 0; ks < 2; ++ks) {
        const int k2b = ks * 8;
        u32 ah[4][4], al[4][4];
        #pragma unroll
        for (int mi = 0; mi < 4; ++mi) {
            const int r = wm * 64 + mi * 16 + g;
            const u32* ph = Ah + r * LDT + k2b + tid;
            const u32* pl = Al + r * LDT + k2b + tid;
            ah[mi][0] = ph[0]; ah[mi][1] = ph[8 * LDT];
            ah[mi][2] = ph[4]; ah[mi][3] = ph[8 * LDT + 4];
            al[mi][0] = pl[0]; al[mi][1] = pl[8 * LDT];
            al[mi][2] = pl[4]; al[mi][3] = pl[8 * LDT + 4];
        }
        #pragma unroll
        for (int ni = 0; ni < 5; ++ni) {
            const int nn = wn * 40 + ni * 8 + g;
            const u32* qh = Bh + nn * LDT + k2b + tid;
            const u32* ql = Bl + nn * LDT + k2b + tid;
            u32 bh[2] = {qh[0], qh[4]};
            u32 bl[2] = {ql[0], ql[4]};
            #pragma unroll
            for (int mi = 0; mi < 4; ++mi) {
                mma16816(acc[mi][ni], ah[mi], bh);
                mma16816(acc[mi][ni], al[mi], bh);
                mma16816(acc[mi][ni], ah[mi], bl);
            }
        }
    }
}

// ===========================================================================
// GEMM1 (HMMA, pipelined): D[n=128,k=160] = x^T·cls ; E=exp(D), colinv, rowpart.
// ===========================================================================
__global__ __launch_bounds__(256) void k_gemm1_mma(
    const float* __restrict__ x, const u16* __restrict__ clsh, const u16* __restrict__ clsl,
    u32* __restrict__ E32, float* __restrict__ colinv, float* __restrict__ rowpart)
{
    __shared__ u32 sAh[128 * LDT], sAl[128 * LDT], sBh[KPAD * LDT], sBl[KPAD * LDT];
    __shared__ float srow[128], skrow[KPAD];
    const int t = threadIdx.x;
    const int wid = t >> 5, lane = t & 31, g = lane >> 2, tid = lane & 3;
    const int wm = wid >> 2, wn = wid & 3;
    const int n0 = blockIdx.x * 128, b = blockIdx.y;
    if (t < 128) srow[t] = 0.f;
    if (t < KPAD) skrow[t] = 0.f;

    float acc[4][5][4] = {};
    const int n = t & 127, half = t >> 7;
    const float* xb = x + (long)b * C * HW + n0 + n;
    const u32* ch32 = (const u32*)clsh;
    const u32* cl32 = (const u32*)clsl;

    float pxa[16];
    u32 pbh[10], pbl[10];
    #pragma unroll
    for (int j = 0; j < 8; ++j) {
        int c = (half * 8 + j) * 2;
        pxa[2 * j] = xb[(long)c * HW]; pxa[2 * j + 1] = xb[(long)(c + 1) * HW];
    }
    #pragma unroll
    for (int ii = 0; ii < 10; ++ii) {
        int i = t + 256 * ii, k = i >> 4, c2 = i & 15;
        pbh[ii] = ch32[k * (C / 2) + c2];
        pbl[ii] = cl32[k * (C / 2) + c2];
    }

    for (int cc = 0; cc < C / KC; ++cc) {
        __syncthreads();
        #pragma unroll
        for (int j = 0; j < 8; ++j) {
            int c2 = half * 8 + j;
            u32 hv, lv;
            split2(pxa[2 * j], pxa[2 * j + 1], &hv, &lv);
            sAh[n * LDT + c2] = hv; sAl[n * LDT + c2] = lv;
        }
        #pragma unroll
        for (int ii = 0; ii < 10; ++ii) {
            int i = t + 256 * ii, k = i >> 4, c2 = i & 15;
            sBh[k * LDT + c2] = pbh[ii]; sBl[k * LDT + c2] = pbl[ii];
        }
        __syncthreads();
        if (cc + 1 < C / KC) {
            #pragma unroll
            for (int j = 0; j < 8; ++j) {
                int c = (cc + 1) * KC + (half * 8 + j) * 2;
                pxa[2 * j] = xb[(long)c * HW]; pxa[2 * j + 1] = xb[(long)(c + 1) * HW];
            }
            #pragma unroll
            for (int ii = 0; ii < 10; ++ii) {
                int i = t + 256 * ii, k = i >> 4, c2 = i & 15;
                pbh[ii] = ch32[k * (C / 2) + (cc + 1) * 16 + c2];
                pbl[ii] = cl32[k * (C / 2) + (cc + 1) * 16 + c2];
            }
        }
        tile_mma(sAh, sAl, sBh, sBl, acc, wm, wn, g, tid);
    }

    #pragma unroll
    for (int mi = 0; mi < 4; ++mi) {
        const int r0 = wm * 64 + mi * 16 + g;
        float s0 = 0.f, s1 = 0.f;
        #pragma unroll
        for (int ni = 0; ni < 5; ++ni) {
            const int cb = wn * 40 + ni * 8 + tid * 2;
            float e0 = __expf(acc[mi][ni][0]);
            float e1 = __expf(acc[mi][ni][1]);
            float e2 = __expf(acc[mi][ni][2]);
            float e3 = __expf(acc[mi][ni][3]);
            float vk0 = 0.f, vk1 = 0.f;
            if (cb < KCLS) {
                E32[((long)b * KCLS + cb) * HW + n0 + r0]     = packE(e0);
                E32[((long)b * KCLS + cb) * HW + n0 + r0 + 8] = packE(e2);
                s0 += e0; s1 += e2; vk0 = e0 + e2;
            }
            if (cb + 1 < KCLS) {
                E32[((long)b * KCLS + cb + 1) * HW + n0 + r0]     = packE(e1);
                E32[((long)b * KCLS + cb + 1) * HW + n0 + r0 + 8] = packE(e3);
                s0 += e1; s1 += e3; vk1 = e1 + e3;
            }
            // reduce row-sum over the 8 g-lanes (n positions), then atom per k
            vk0 += __shfl_xor_sync(0xFFFFFFFFu, vk0, 4);
            vk0 += __shfl_xor_sync(0xFFFFFFFFu, vk0, 8);
            vk0 += __shfl_xor_sync(0xFFFFFFFFu, vk0, 16);
            vk1 += __shfl_xor_sync(0xFFFFFFFFu, vk1, 4);
            vk1 += __shfl_xor_sync(0xFFFFFFFFu, vk1, 8);
            vk1 += __shfl_xor_sync(0xFFFFFFFFu, vk1, 16);
            if (g == 0 && cb < KCLS) {
                atomicAdd(&skrow[cb], vk0);
                if (cb + 1 < KCLS) atomicAdd(&skrow[cb + 1], vk1);
            }
        }
        atomicAdd(&srow[r0], s0);
        atomicAdd(&srow[r0 + 8], s1);
    }
    __syncthreads();
    if (t < 128) colinv[(long)b * HW + n0 + t] = 1.f / srow[t];
    if (t < KPAD)
        rowpart[((long)b * KPAD + t) * (HW / 128) + blockIdx.x] = skrow[t];
}

// ===========================================================================
// pool (HMMA, pipelined): D[c=128,k=160] = sum_n x[c,n]*E[k,n]  (split-K)
// ===========================================================================
__global__ __launch_bounds__(256) void k_pool_mma(
    const float* __restrict__ x, const u32* __restrict__ E32, float* __restrict__ poolpart)
{
    __shared__ u32 sAh[128 * LDT], sAl[128 * LDT], sBh[KPAD * LDT], sBl[KPAD * LDT];
    const int t = threadIdx.x;
    const int wid = t >> 5, lane = t & 31, g = lane >> 2, tid = lane & 3;
    const int wm = wid >> 2, wn = wid & 3;
    const int c0 = blockIdx.x * 128, sp = blockIdx.y, b = blockIdx.z;
    const int nbase = sp * (HW / NSPLIT);
    float acc[4][5][4] = {};

    float2 pf2[8];
    u32 pw0[10], pw1[10];
    {
        const int nb = nbase;
        #pragma unroll
        for (int ii = 0; ii < 8; ++ii) {
            int i = t + 256 * ii, r = i >> 4, c2 = i & 15;
            pf2[ii] = *(const float2*)(x + ((long)b * C + c0 + r) * HW + nb + c2 * 2);
        }
        #pragma unroll
        for (int ii = 0; ii < 10; ++ii) {
            int i = t + 256 * ii, k = i >> 4, c2 = i & 15;
            if (k < KCLS) {
                const u32* p = E32 + ((long)b * KCLS + k) * HW + nb + c2 * 2;
                pw0[ii] = p[0]; pw1[ii] = p[1];
            } else { pw0[ii] = 0; pw1[ii] = 0; }
        }
    }

    for (int nn = 0; nn < HW / NSPLIT; nn += KC) {
        __syncthreads();
        #pragma unroll
        for (int ii = 0; ii < 8; ++ii) {
            int i = t + 256 * ii, r = i >> 4, c2 = i & 15;
            u32 hv, lv;
            split2(pf2[ii].x, pf2[ii].y, &hv, &lv);
            sAh[r * LDT + c2] = hv; sAl[r * LDT + c2] = lv;
        }
        #pragma unroll
        for (int ii = 0; ii < 10; ++ii) {
            int i = t + 256 * ii, k = i >> 4, c2 = i & 15;
            sBh[k * LDT + c2] = __byte_perm(pw0[ii], pw1[ii], 0x5410);
            sBl[k * LDT + c2] = __byte_perm(pw0[ii], pw1[ii], 0x7632);
        }
        __syncthreads();
        if (nn + KC < HW / NSPLIT) {
            const int nb = nbase + nn + KC;
            #pragma unroll
            for (int ii = 0; ii < 8; ++ii) {
                int i = t + 256 * ii, r = i >> 4, c2 = i & 15;
                pf2[ii] = *(const float2*)(x + ((long)b * C + c0 + r) * HW + nb + c2 * 2);
            }
            #pragma unroll
            for (int ii = 0; ii < 10; ++ii) {
                int i = t + 256 * ii, k = i >> 4, c2 = i & 15;
                if (k < KCLS) {
                    const u32* p = E32 + ((long)b * KCLS + k) * HW + nb + c2 * 2;
                    pw0[ii] = p[0]; pw1[ii] = p[1];
                } else { pw0[ii] = 0; pw1[ii] = 0; }
            }
        }
        tile_mma(sAh, sAl, sBh, sBl, acc, wm, wn, g, tid);
    }

    const long base = ((long)sp * BATCH + b) * KCLS;
    #pragma unroll
    for (int mi = 0; mi < 4; ++mi) {
        const int r0 = wm * 64 + mi * 16 + g;
        #pragma unroll
        for (int ni = 0; ni < 5; ++ni) {
            const int cb = wn * 40 + ni * 8 + tid * 2;
            if (cb < KCLS) {
                poolpart[(base + cb) * C + c0 + r0]     = acc[mi][ni][0];
                poolpart[(base + cb) * C + c0 + r0 + 8] = acc[mi][ni][2];
            }
            if (cb + 1 < KCLS) {
                poolpart[(base + cb + 1) * C + c0 + r0]     = acc[mi][ni][1];
                poolpart[(base + cb + 1) * C + c0 + r0 + 8] = acc[mi][ni][3];
            }
        }
    }
}

// ===========================================================================
// masks (HMMA, pipelined): D[n=128,k=160] = x^T·acls + pos_attn·G^T, then LN.
// ===========================================================================
__global__ __launch_bounds__(256) void k_masks_mma(
    const float* __restrict__ x, const u16* __restrict__ aclsh, const u16* __restrict__ aclsl,
    const u16* __restrict__ Gh, const u16* __restrict__ Gl,
    const u32* __restrict__ E32, const float* __restrict__ colinv,
    const float* __restrict__ gamma, const float* __restrict__ beta,
    float* __restrict__ out)
{
    __shared__ u32 sAh[128 * LDT], sAl[128 * LDT], sBh[KPAD * LDT], sBl[KPAD * LDT];
    __shared__ float ssum[128], ssq[128], civ[128], gam[KCLS], bet[KCLS];
    const int t = threadIdx.x;
    const int wid = t >> 5, lane = t & 31, g = lane >> 2, tid = lane & 3;
    const int wm = wid >> 2, wn = wid & 3;
    const int n0 = blockIdx.x * 128, b = blockIdx.y;
    if (t < 128) {
        ssum[t] = 0.f; ssq[t] = 0.f;
        civ[t] = colinv[(long)b * HW + n0 + t];
    }
    for (int i = t; i < KCLS; i += 256) { gam[i] = gamma[i]; bet[i] = beta[i]; }

    float acc[4][5][4] = {};
    const int n = t & 127, half = t >> 7;
    const float* xb = x + (long)b * C * HW + n0 + n;
    const u32* ah32 = (const u32*)(aclsh + (long)b * KPAD * C);
    const u32* al32 = (const u32*)(aclsl + (long)b * KPAD * C);
    const u32* gh32 = (const u32*)(Gh + (long)b * KPAD * KP2);
    const u32* gl32 = (const u32*)(Gl + (long)b * KPAD * KP2);

    float pxa[16];
    u32 pbh[10], pbl[10];
    #pragma unroll
    for (int j = 0; j < 8; ++j) {
        int c = (half * 8 + j) * 2;
        pxa[2 * j] = xb[(long)c * HW]; pxa[2 * j + 1] = xb[(long)(c + 1) * HW];
    }
    #pragma unroll
    for (int ii = 0; ii < 10; ++ii) {
        int i = t + 256 * ii, k = i >> 4, c2 = i & 15;
        if (k < KCLS) { pbh[ii] = ah32[k * (C / 2) + c2]; pbl[ii] = al32[k * (C / 2) + c2]; }
        else { pbh[ii] = 0; pbl[ii] = 0; }
    }

    // phase 1: reduction over c  (A = x^T, B = acls)
    for (int cc = 0; cc < C / KC; ++cc) {
        __syncthreads();
        #pragma unroll
        for (int j = 0; j < 8; ++j) {
            int c2 = half * 8 + j;
            u32 hv, lv;
            split2(pxa[2 * j], pxa[2 * j + 1], &hv, &lv);
            sAh[n * LDT + c2] = hv; sAl[n * LDT + c2] = lv;
        }
        #pragma unroll
        for (int ii = 0; ii < 10; ++ii) {
            int i = t + 256 * ii, k = i >> 4, c2 = i & 15;
            sBh[k * LDT + c2] = pbh[ii]; sBl[k * LDT + c2] = pbl[ii];
        }
        __syncthreads();
        if (cc + 1 < C / KC) {
            #pragma unroll
            for (int j = 0; j < 8; ++j) {
                int c = (cc + 1) * KC + (half * 8 + j) * 2;
                pxa[2 * j] = xb[(long)c * HW]; pxa[2 * j + 1] = xb[(long)(c + 1) * HW];
            }
            #pragma unroll
            for (int ii = 0; ii < 10; ++ii) {
                int i = t + 256 * ii, k = i >> 4, c2 = i & 15;
                if (k < KCLS) {
                    pbh[ii] = ah32[k * (C / 2) + (cc + 1) * 16 + c2];
                    pbl[ii] = al32[k * (C / 2) + (cc + 1) * 16 + c2];
                } else { pbh[ii] = 0; pbl[ii] = 0; }
            }
        } else {
            // prefetch phase-2 chunk 0
            #pragma unroll
            for (int j = 0; j < 8; ++j) {
                int kq = (half * 8 + j) * 2;
                pxa[2 * j] = (kq < KCLS) ?
                    unpackE(E32[((long)b * KCLS + kq) * HW + n0 + n]) : 0.f;
                pxa[2 * j + 1] = (kq + 1 < KCLS) ?
                    unpackE(E32[((long)b * KCLS + kq + 1) * HW + n0 + n]) : 0.f;
            }
            #pragma unroll
            for (int ii = 0; ii < 10; ++ii) {
                int i = t + 256 * ii, k = i >> 4, c2 = i & 15;
                pbh[ii] = gh32[k * (KP2 / 2) + c2];
                pbl[ii] = gl32[k * (KP2 / 2) + c2];
            }
        }
        tile_mma(sAh, sAl, sBh, sBl, acc, wm, wn, g, tid);
    }
    // phase 2: reduction over k'  (A = pos_attn, B = G)
    const float ci = civ[n];
    for (int pc = 0; pc < KP2 / KC; ++pc) {
        __syncthreads();
        #pragma unroll
        for (int j = 0; j < 8; ++j) {
            int q2 = half * 8 + j;
            u32 hv, lv;
            split2(pxa[2 * j] * ci, pxa[2 * j + 1] * ci, &hv, &lv);
            sAh[n * LDT + q2] = hv; sAl[n * LDT + q2] = lv;
        }
        #pragma unroll
        for (int ii = 0; ii < 10; ++ii) {
            int i = t + 256 * ii, k = i >> 4, c2 = i & 15;
            sBh[k * LDT + c2] = pbh[ii]; sBl[k * LDT + c2] = pbl[ii];
        }
        __syncthreads();
        if (pc + 1 < KP2 / KC) {
            #pragma unroll
            for (int j = 0; j < 8; ++j) {
                int kq = (pc + 1) * KC + (half * 8 + j) * 2;
                pxa[2 * j] = (kq < KCLS) ?
                    unpackE(E32[((long)b * KCLS + kq) * HW + n0 + n]) : 0.f;
                pxa[2 * j + 1] = (kq + 1 < KCLS) ?
                    unpackE(E32[((long)b * KCLS + kq + 1) * HW + n0 + n]) : 0.f;
            }
            #pragma unroll
            for (int ii = 0; ii < 10; ++ii) {
                int i = t + 256 * ii, k = i >> 4, c2 = i & 15;
                pbh[ii] = gh32[k * (KP2 / 2) + (pc + 1) * 16 + c2];
                pbl[ii] = gl32[k * (KP2 / 2) + (pc + 1) * 16 + c2];
            }
        }
        tile_mma(sAh, sAl, sBh, sBl, acc, wm, wn, g, tid);
    }

    // LayerNorm stats over k (<150) via smem atomics
    #pragma unroll
    for (int mi = 0; mi < 4; ++mi) {
        const int r0 = wm * 64 + mi * 16 + g;
        float s0 = 0.f, q0 = 0.f, s1 = 0.f, q1 = 0.f;
        #pragma unroll
        for (int ni = 0; ni < 5; ++ni) {
            const int cb = wn * 40 + ni * 8 + tid * 2;
            if (cb < KCLS) {
                float v = acc[mi][ni][0]; s0 += v; q0 += v * v;
                v = acc[mi][ni][2]; s1 += v; q1 += v * v;
            }
            if (cb + 1 < KCLS) {
                float v = acc[mi][ni][1]; s0 += v; q0 += v * v;
                v = acc[mi][ni][3]; s1 += v; q1 += v * v;
            }
        }
        atomicAdd(&ssum[r0], s0); atomicAdd(&ssq[r0], q0);
        atomicAdd(&ssum[r0 + 8], s1); atomicAdd(&ssq[r0 + 8], q1);
    }
    __syncthreads();
    #pragma unroll
    for (int mi = 0; mi < 4; ++mi) {
        const int r0 = wm * 64 + mi * 16 + g;
        const float mu0 = ssum[r0] * (1.f / KCLS);
        const float rs0 = rsqrtf(ssq[r0] * (1.f / KCLS) - mu0 * mu0 + 1e-5f);
        const float mu1 = ssum[r0 + 8] * (1.f / KCLS);
        const float rs1 = rsqrtf(ssq[r0 + 8] * (1.f / KCLS) - mu1 * mu1 + 1e-5f);
        #pragma unroll
        for (int ni = 0; ni < 5; ++ni) {
            const int cb = wn * 40 + ni * 8 + tid * 2;
            if (cb < KCLS) {
                out[((long)b * KCLS + cb) * HW + n0 + r0] =
                    (acc[mi][ni][0] - mu0) * rs0 * gam[cb] + bet[cb];
                out[((long)b * KCLS + cb) * HW + n0 + r0 + 8] =
                    (acc[mi][ni][2] - mu1) * rs1 * gam[cb] + bet[cb];
            }
            if (cb + 1 < KCLS) {
                out[((long)b * KCLS + cb + 1) * HW + n0 + r0] =
                    (acc[mi][ni][1] - mu0) * rs0 * gam[cb + 1] + bet[cb + 1];
                out[((long)b * KCLS + cb + 1) * HW + n0 + r0 + 8] =
                    (acc[mi][ni][3] - mu1) * rs1 * gam[cb + 1] + bet[cb + 1];
            }
        }
    }
}

// ===========================================================================
// SIMT small kernels
// ===========================================================================
__global__ void k_prep(const float* __restrict__ cls, u16* __restrict__ ch_, u16* __restrict__ cl_)
{
    int i = blockIdx.x * 256 + threadIdx.x;
    if (i < KPAD * C) {
        float v = (i < KCLS * C) ? cls[i] : 0.f;
        u32 u = __float_as_uint(v);
        float l = v - __uint_as_float(u & 0xFFFF0000u);
        ch_[i] = (u16)(u >> 16);
        cl_[i] = (u16)(__float_as_uint(l) >> 16);
    }
}

__global__ void k_rowred(const float* __restrict__ rowpart, float* __restrict__ rinv)
{
    int idx = blockIdx.x * 256 + threadIdx.x;
    if (idx < BATCH * KPAD) {
        const float* p = rowpart + (long)idx * (HW / 128);
        float s = 0.f;
        for (int i = 0; i < HW / 128; ++i) s += p[i];
        rinv[idx] = 1.f / s;
    }
}

__device__ __forceinline__ void sg_body(
    const float* __restrict__ A, int arow_valid, const float* __restrict__ W, int brow_valid,
    float acc[4][4], int t, float As[16][64], float Bs[16][64])
{
    const int tm = (t >> 4) * 4, tn = (t & 15) * 4;
    const int ar = t >> 2, ac = (t & 3) * 4;
    const int bc = t >> 2, bp = (t & 3) * 4;
    for (int p0 = 0; p0 < C; p0 += 16) {
        float4 av = make_float4(0.f, 0.f, 0.f, 0.f);
        if (ar < arow_valid) av = *(const float4*)&A[(long)ar * C + p0 + ac];
        As[ac + 0][ar] = av.x; As[ac + 1][ar] = av.y; As[ac + 2][ar] = av.z; As[ac + 3][ar] = av.w;
        float4 bv = make_float4(0.f, 0.f, 0.f, 0.f);
        if (bc < brow_valid) bv = *(const float4*)&W[(long)bc * C + p0 + bp];
        Bs[bp + 0][bc] = bv.x; Bs[bp + 1][bc] = bv.y; Bs[bp + 2][bc] = bv.z; Bs[bp + 3][bc] = bv.w;
        __syncthreads();
        #pragma unroll
        for (int kk = 0; kk < 16; ++kk) {
            float4 a4 = *(const float4*)&As[kk][tm];
            float4 b4 = *(const float4*)&Bs[kk][tn];
            float aa[4] = {a4.x, a4.y, a4.z, a4.w};
            float bb[4] = {b4.x, b4.y, b4.z, b4.w};
            #pragma unroll
            for (int i = 0; i < 4; ++i)
                #pragma unroll
                for (int j = 0; j < 4; ++j)
                    acc[i][j] = fmaf(aa[i], bb[j], acc[i][j]);
        }
        __syncthreads();
    }
}

__global__ __launch_bounds__(256) void k_clsWf(
    const float* __restrict__ cls, const float* __restrict__ W, float* __restrict__ outw)
{
    __shared__ float As[16][64], Bs[16][64];
    const int t = threadIdx.x, k0 = blockIdx.x * 64, c0 = blockIdx.y * 64;
    float acc[4][4] = {};
    int av = KCLS - k0; av = av > 64 ? 64 : (av > 0 ? av : 0);
    sg_body(cls + (long)k0 * C, av, W + (long)c0 * C, 64, acc, t, As, Bs);
    const int tm = (t >> 4) * 4, tn = (t & 15) * 4;
    #pragma unroll
    for (int i = 0; i < 4; ++i) {
        int k = k0 + tm + i;
        if (k < KCLS)
            *(float4*)&outw[(long)k * C + c0 + tn] =
                make_float4(acc[i][0], acc[i][1], acc[i][2], acc[i][3]);
    }
}

__global__ __launch_bounds__(256) void k_acls(
    const float* __restrict__ poolpart, const float* __restrict__ rinv,
    const float* __restrict__ W, const float* __restrict__ cls,
    float* __restrict__ outf, u16* __restrict__ outh, u16* __restrict__ outl)
{
    __shared__ float As[16][64], Bs[16][64];
    const int t = threadIdx.x;
    const int k0 = blockIdx.x * 64, c0 = blockIdx.y * 64, b = blockIdx.z;
    const int tm = (t >> 4) * 4, tn = (t & 15) * 4;
    const int ar = t >> 2, ac = (t & 3) * 4;
    const int bc = t >> 2, bp = (t & 3) * 4;
    float acc[4][4] = {};
    const int ka = k0 + ar;
    const float rv = (ka < KCLS) ? rinv[b * KPAD + ka] : 0.f;

    for (int p0 = 0; p0 < C; p0 += 16) {
        float4 av = make_float4(0.f, 0.f, 0.f, 0.f);
        if (ka < KCLS) {
            #pragma unroll
            for (int s = 0; s < NSPLIT; ++s) {
                float4 v = *(const float4*)
                    &poolpart[(((long)s * BATCH + b) * KCLS + ka) * C + p0 + ac];
                av.x += v.x; av.y += v.y; av.z += v.z; av.w += v.w;
            }
            av.x *= rv; av.y *= rv; av.z *= rv; av.w *= rv;
        }
        As[ac + 0][ar] = av.x; As[ac + 1][ar] = av.y; As[ac + 2][ar] = av.z; As[ac + 3][ar] = av.w;
        float4 bv = *(const float4*)&W[(long)(c0 + bc) * C + p0 + bp];
        Bs[bp + 0][bc] = bv.x; Bs[bp + 1][bc] = bv.y; Bs[bp + 2][bc] = bv.z; Bs[bp + 3][bc] = bv.w;
        __syncthreads();
        #pragma unroll
        for (int kk = 0; kk < 16; ++kk) {
            float4 a4 = *(const float4*)&As[kk][tm];
            float4 b4 = *(const float4*)&Bs[kk][tn];
            float aa[4] = {a4.x, a4.y, a4.z, a4.w};
            float bb[4] = {b4.x, b4.y, b4.z, b4.w};
            #pragma unroll
            for (int i = 0; i < 4; ++i)
                #pragma unroll
                for (int j = 0; j < 4; ++j)
                    acc[i][j] = fmaf(aa[i], bb[j], acc[i][j]);
        }
        __syncthreads();
    }
    #pragma unroll
    for (int i = 0; i < 4; ++i) {
        int k = k0 + tm + i;
        if (k < KCLS) {
            #pragma unroll
            for (int j = 0; j < 4; ++j) {
                float v = acc[i][j] + cls[(long)k * C + c0 + tn + j];
                outf[((long)b * KCLS + k) * C + c0 + tn + j] = v;
                long po = ((long)b * KPAD + k) * C + c0 + tn + j;
                u32 u = __float_as_uint(v);
                float l = v - __uint_as_float(u & 0xFFFF0000u);
                outh[po] = (u16)(u >> 16);
                outl[po] = (u16)(__float_as_uint(l) >> 16);
            }
        }
    }
}

__global__ __launch_bounds__(256) void k_G(
    const float* __restrict__ acls, const float* __restrict__ clsWf,
    u16* __restrict__ Gh, u16* __restrict__ Gl)
{
    __shared__ float As[16][64], Bs[16][64];
    const int t = threadIdx.x;
    const int k0 = blockIdx.x * 64, k20 = blockIdx.y * 64, b = blockIdx.z;
    float acc[4][4] = {};
    int av = KCLS - k0; av = av > 64 ? 64 : (av > 0 ? av : 0);
    int bv = KCLS - k20; bv = bv > 64 ? 64 : (bv > 0 ? bv : 0);
    sg_body(acls + ((long)b * KCLS + k0) * C, av, clsWf + (long)k20 * C, bv, acc, t, As, Bs);
    const int tm = (t >> 4) * 4, tn = (t & 15) * 4;
    #pragma unroll
    for (int i = 0; i < 4; ++i) {
        int k = k0 + tm + i;
        if (k < KPAD) {
            #pragma unroll
            for (int j = 0; j < 4; ++j) {
                float v = acc[i][j];
                long po = ((long)b * KPAD + k) * KP2 + k20 + tn + j;
                u32 u = __float_as_uint(v);
                float l = v - __uint_as_float(u & 0xFFFF0000u);
                Gh[po] = (u16)(u >> 16);
                Gl[po] = (u16)(__float_as_uint(l) >> 16);
            }
        }
    }
}

// ===========================================================================
extern "C" void kernel_launch(void* const* d_in, const int* in_sizes, int n_in,
                              void* d_out, int out_size)
{
    const float* x     = (const float*)d_in[0];
    const float* cls   = (const float*)d_in[1];
    const float* Wcls  = (const float*)d_in[2];
    const float* Wfeat = (const float*)d_in[3];
    const float* gamma = (const float*)d_in[4];
    const float* beta  = (const float*)d_in[5];
    float* out = (float*)d_out;

    u16 *clsh, *clsl, *aclsh, *aclsl, *Gh, *Gl;
    u32* E32;
    float *colinv, *rowpart, *rinv, *poolpart, *acls, *clsWf;
    cudaGetSymbolAddress((void**)&clsh,  g_clsh);
    cudaGetSymbolAddress((void**)&clsl,  g_clsl);
    cudaGetSymbolAddress((void**)&E32,   g_E32);
    cudaGetSymbolAddress((void**)&colinv, g_colinv);
    cudaGetSymbolAddress((void**)&rowpart, g_rowpart);
    cudaGetSymbolAddress((void**)&rinv,  g_rinv);
    cudaGetSymbolAddress((void**)&poolpart, g_poolpart);
    cudaGetSymbolAddress((void**)&acls,  g_acls);
    cudaGetSymbolAddress((void**)&aclsh, g_aclsh);
    cudaGetSymbolAddress((void**)&aclsl, g_aclsl);
    cudaGetSymbolAddress((void**)&clsWf, g_clsWf);
    cudaGetSymbolAddress((void**)&Gh,    g_Gh);
    cudaGetSymbolAddress((void**)&Gl,    g_Gl);

    k_prep<<<(KPAD * C + 255) / 256, 256>>>(cls, clsh, clsl);
    k_gemm1_mma<<<dim3(HW / 128, BATCH), 256>>>(x, clsh, clsl, E32, colinv, rowpart);
    k_rowred<<<(BATCH * KPAD + 255) / 256, 256>>>(rowpart, rinv);
    k_pool_mma<<<dim3(C / 128, NSPLIT, BATCH), 256>>>(x, E32, poolpart);
    k_clsWf<<<dim3(3, C / 64), 256>>>(cls, Wfeat, clsWf);
    k_acls<<<dim3(3, C / 64, BATCH), 256>>>(poolpart, rinv, Wcls, cls, acls, aclsh, aclsl);
    k_G<<<dim3(3, 3, BATCH), 256>>>(acls, clsWf, Gh, Gl);
    k_masks_mma<<<dim3(HW / 128, BATCH), 256>>>(
        x, aclsh, aclsl, Gh, Gl, E32, colinv, gamma, beta, out);
}

// round 7
// speedup vs baseline: 2.6405x; 1.0926x over previous
#include <cuda_runtime.h>
#include <stdint.h>

#define BATCH 8
#define C 512
#define HW 16384
#define KCLS 150
#define KPAD 160
#define KP2 192
#define NSPLIT 16
#define KC 32
#define LDT 20   // u32 row stride of smem tiles (conflict-free fragment reads)

typedef unsigned int u32;
typedef unsigned short u16;

// ---------------- scratch (device globals; no allocations) ----------------
__device__ u16  g_clsh[KPAD * C];
__device__ u16  g_clsl[KPAD * C];
__device__ u32  g_E32[(long)BATCH * KCLS * HW];  // packed: hi bf16 (low16) | lo bf16 (high16)
__device__ float g_colinv[BATCH * HW];
__device__ float g_rowpart[(long)BATCH * KPAD * (HW / 128)];
__device__ float g_rinv[BATCH * KPAD];
__device__ float g_poolpart[(long)NSPLIT * BATCH * KCLS * C];
__device__ float g_acls[BATCH * KCLS * C];
__device__ u16  g_aclsh[BATCH * KPAD * C];
__device__ u16  g_aclsl[BATCH * KPAD * C];
__device__ float g_clsWf[KCLS * C];
__device__ u16  g_Gh[BATCH * KPAD * KP2];
__device__ u16  g_Gl[BATCH * KPAD * KP2];

// ---------------- helpers ----------------
__device__ __forceinline__ int aidx(int r, int c2) {
    // A-tile layout: stride-20 rows + nibble rotation (low 2 bits) by octet.
    return r * LDT + ((((c2) + (r >> 3)) & 3) | ((c2) & 12));
}
__device__ __forceinline__ void split2(float v0, float v1, u32* hv, u32* lv) {
    u32 u0 = __float_as_uint(v0), u1 = __float_as_uint(v1);
    float l0 = v0 - __uint_as_float(u0 & 0xFFFF0000u);
    float l1 = v1 - __uint_as_float(u1 & 0xFFFF0000u);
    *hv = __byte_perm(u0, u1, 0x7632);
    *lv = __byte_perm(__float_as_uint(l0), __float_as_uint(l1), 0x7632);
}
__device__ __forceinline__ u32 packE(float e) {
    u32 u = __float_as_uint(e);
    float lo = e - __uint_as_float(u & 0xFFFF0000u);
    return (u >> 16) | (__float_as_uint(lo) & 0xFFFF0000u);
}
__device__ __forceinline__ float unpackE(u32 w) {
    return __uint_as_float((w & 0xFFFFu) << 16) + __uint_as_float(w & 0xFFFF0000u);
}
__device__ __forceinline__ void mma16816(float c[4], const u32 a[4], const u32 b[2]) {
    asm volatile(
        "mma.sync.aligned.m16n8k16.row.col.f32.bf16.bf16.f32 "
        "{%0,%1,%2,%3}, {%4,%5,%6,%7}, {%8,%9}, {%0,%1,%2,%3};"
        : "+f"(c[0]), "+f"(c[1]), "+f"(c[2]), "+f"(c[3])
        : "r"(a[0]), "r"(a[1]), "r"(a[2]), "r"(a[3]), "r"(b[0]), "r"(b[1]));
}

// Compute the 128x160 CTA tile's contribution for one K-chunk of 32.
// Warp (wm,wn) owns rows [wm*64, +64), cols [wn*40, +40).
__device__ __forceinline__ void tile_mma(
    const u32* __restrict__ Ah, const u32* __restrict__ Al,
    const u32* __restrict__ Bh, const u32* __restrict__ Bl,
    float (*acc)[5][4], int wm, int wn, int g, int tid)
{
    #pragma unroll
    for (int ks = 0; ks < 2; ++ks) {
        const int k2b = ks * 8;
        u32 ah[4][4], al[4][4];
        #pragma unroll
        for (int mi = 0; mi < 4; ++mi) {
            const int r = wm * 64 + mi * 16 + g;
            const int i0 = aidx(r, k2b + tid);
            const int i1 = aidx(r + 8, k2b + tid);
            ah[mi][0] = Ah[i0];     ah[mi][1] = Ah[i1];
            ah[mi][2] = Ah[i0 + 4]; ah[mi][3] = Ah[i1 + 4];
            al[mi][0] = Al[i0];     al[mi][1] = Al[i1];
            al[mi][2] = Al[i0 + 4]; al[mi][3] = Al[i1 + 4];
        }
        #pragma unroll
        for (int ni = 0; ni < 5; ++ni) {
            const int nn = wn * 40 + ni * 8 + g;
            const u32* qh = Bh + nn * LDT + k2b + tid;
            const u32* ql = Bl + nn * LDT + k2b + tid;
            u32 bh[2] = {qh[0], qh[4]};
            u32 bl[2] = {ql[0], ql[4]};
            #pragma unroll
            for (int mi = 0; mi < 4; ++mi) {
                mma16816(acc[mi][ni], ah[mi], bh);
                mma16816(acc[mi][ni], al[mi], bh);
                mma16816(acc[mi][ni], ah[mi], bl);
            }
        }
    }
}

// ===========================================================================
// GEMM1 (HMMA, pipelined): D[n=128,k=160] = x^T·cls ; E=exp(D), colinv, rowpart.
// ===========================================================================
__global__ __launch_bounds__(256) void k_gemm1_mma(
    const float* __restrict__ x, const u16* __restrict__ clsh, const u16* __restrict__ clsl,
    u32* __restrict__ E32, float* __restrict__ colinv, float* __restrict__ rowpart)
{
    __shared__ u32 sAh[128 * LDT], sAl[128 * LDT], sBh[KPAD * LDT], sBl[KPAD * LDT];
    __shared__ float srow[128], skrow[KPAD];
    const int t = threadIdx.x;
    const int wid = t >> 5, lane = t & 31, g = lane >> 2, tid = lane & 3;
    const int wm = wid >> 2, wn = wid & 3;
    const int n0 = blockIdx.x * 128, b = blockIdx.y;
    if (t < 128) srow[t] = 0.f;
    if (t < KPAD) skrow[t] = 0.f;

    float acc[4][5][4] = {};
    const int n = t & 127, half = t >> 7;
    const float* xb = x + (long)b * C * HW + n0 + n;
    const u32* ch32 = (const u32*)clsh;
    const u32* cl32 = (const u32*)clsl;

    float pxa[16];
    u32 pbh[10], pbl[10];
    #pragma unroll
    for (int j = 0; j < 8; ++j) {
        int c = (half * 8 + j) * 2;
        pxa[2 * j] = xb[(long)c * HW]; pxa[2 * j + 1] = xb[(long)(c + 1) * HW];
    }
    #pragma unroll
    for (int ii = 0; ii < 10; ++ii) {
        int i = t + 256 * ii, k = i >> 4, c2 = i & 15;
        pbh[ii] = ch32[k * (C / 2) + c2];
        pbl[ii] = cl32[k * (C / 2) + c2];
    }

    for (int cc = 0; cc < C / KC; ++cc) {
        __syncthreads();
        #pragma unroll
        for (int j = 0; j < 8; ++j) {
            int c2 = half * 8 + j;
            u32 hv, lv;
            split2(pxa[2 * j], pxa[2 * j + 1], &hv, &lv);
            int ix = aidx(n, c2);
            sAh[ix] = hv; sAl[ix] = lv;
        }
        #pragma unroll
        for (int ii = 0; ii < 10; ++ii) {
            int i = t + 256 * ii, k = i >> 4, c2 = i & 15;
            sBh[k * LDT + c2] = pbh[ii]; sBl[k * LDT + c2] = pbl[ii];
        }
        __syncthreads();
        if (cc + 1 < C / KC) {
            #pragma unroll
            for (int j = 0; j < 8; ++j) {
                int c = (cc + 1) * KC + (half * 8 + j) * 2;
                pxa[2 * j] = xb[(long)c * HW]; pxa[2 * j + 1] = xb[(long)(c + 1) * HW];
            }
            #pragma unroll
            for (int ii = 0; ii < 10; ++ii) {
                int i = t + 256 * ii, k = i >> 4, c2 = i & 15;
                pbh[ii] = ch32[k * (C / 2) + (cc + 1) * 16 + c2];
                pbl[ii] = cl32[k * (C / 2) + (cc + 1) * 16 + c2];
            }
        }
        tile_mma(sAh, sAl, sBh, sBl, acc, wm, wn, g, tid);
    }

    #pragma unroll
    for (int mi = 0; mi < 4; ++mi) {
        const int r0 = wm * 64 + mi * 16 + g;
        float s0 = 0.f, s1 = 0.f;
        #pragma unroll
        for (int ni = 0; ni < 5; ++ni) {
            const int cb = wn * 40 + ni * 8 + tid * 2;
            float e0 = __expf(acc[mi][ni][0]);
            float e1 = __expf(acc[mi][ni][1]);
            float e2 = __expf(acc[mi][ni][2]);
            float e3 = __expf(acc[mi][ni][3]);
            float vk0 = 0.f, vk1 = 0.f;
            if (cb < KCLS) {
                E32[((long)b * KCLS + cb) * HW + n0 + r0]     = packE(e0);
                E32[((long)b * KCLS + cb) * HW + n0 + r0 + 8] = packE(e2);
                s0 += e0; s1 += e2; vk0 = e0 + e2;
            }
            if (cb + 1 < KCLS) {
                E32[((long)b * KCLS + cb + 1) * HW + n0 + r0]     = packE(e1);
                E32[((long)b * KCLS + cb + 1) * HW + n0 + r0 + 8] = packE(e3);
                s0 += e1; s1 += e3; vk1 = e1 + e3;
            }
            vk0 += __shfl_xor_sync(0xFFFFFFFFu, vk0, 4);
            vk0 += __shfl_xor_sync(0xFFFFFFFFu, vk0, 8);
            vk0 += __shfl_xor_sync(0xFFFFFFFFu, vk0, 16);
            vk1 += __shfl_xor_sync(0xFFFFFFFFu, vk1, 4);
            vk1 += __shfl_xor_sync(0xFFFFFFFFu, vk1, 8);
            vk1 += __shfl_xor_sync(0xFFFFFFFFu, vk1, 16);
            if (g == 0 && cb < KCLS) {
                atomicAdd(&skrow[cb], vk0);
                if (cb + 1 < KCLS) atomicAdd(&skrow[cb + 1], vk1);
            }
        }
        atomicAdd(&srow[r0], s0);
        atomicAdd(&srow[r0 + 8], s1);
    }
    __syncthreads();
    if (t < 128) colinv[(long)b * HW + n0 + t] = 1.f / srow[t];
    if (t < KPAD)
        rowpart[((long)b * KPAD + t) * (HW / 128) + blockIdx.x] = skrow[t];
}

// ===========================================================================
// pool (HMMA, pipelined): D[c=128,k=160] = sum_n x[c,n]*E[k,n]  (split-K)
// ===========================================================================
__global__ __launch_bounds__(256) void k_pool_mma(
    const float* __restrict__ x, const u32* __restrict__ E32, float* __restrict__ poolpart)
{
    __shared__ u32 sAh[128 * LDT], sAl[128 * LDT], sBh[KPAD * LDT], sBl[KPAD * LDT];
    const int t = threadIdx.x;
    const int wid = t >> 5, lane = t & 31, g = lane >> 2, tid = lane & 3;
    const int wm = wid >> 2, wn = wid & 3;
    const int c0 = blockIdx.x * 128, sp = blockIdx.y, b = blockIdx.z;
    const int nbase = sp * (HW / NSPLIT);
    float acc[4][5][4] = {};

    float2 pf2[8];
    u32 pw0[10], pw1[10];
    {
        const int nb = nbase;
        #pragma unroll
        for (int ii = 0; ii < 8; ++ii) {
            int i = t + 256 * ii, r = i >> 4, c2 = i & 15;
            pf2[ii] = *(const float2*)(x + ((long)b * C + c0 + r) * HW + nb + c2 * 2);
        }
        #pragma unroll
        for (int ii = 0; ii < 10; ++ii) {
            int i = t + 256 * ii, k = i >> 4, c2 = i & 15;
            if (k < KCLS) {
                const u32* p = E32 + ((long)b * KCLS + k) * HW + nb + c2 * 2;
                pw0[ii] = p[0]; pw1[ii] = p[1];
            } else { pw0[ii] = 0; pw1[ii] = 0; }
        }
    }

    for (int nn = 0; nn < HW / NSPLIT; nn += KC) {
        __syncthreads();
        #pragma unroll
        for (int ii = 0; ii < 8; ++ii) {
            int i = t + 256 * ii, r = i >> 4, c2 = i & 15;
            u32 hv, lv;
            split2(pf2[ii].x, pf2[ii].y, &hv, &lv);
            int ix = aidx(r, c2);
            sAh[ix] = hv; sAl[ix] = lv;
        }
        #pragma unroll
        for (int ii = 0; ii < 10; ++ii) {
            int i = t + 256 * ii, k = i >> 4, c2 = i & 15;
            sBh[k * LDT + c2] = __byte_perm(pw0[ii], pw1[ii], 0x5410);
            sBl[k * LDT + c2] = __byte_perm(pw0[ii], pw1[ii], 0x7632);
        }
        __syncthreads();
        if (nn + KC < HW / NSPLIT) {
            const int nb = nbase + nn + KC;
            #pragma unroll
            for (int ii = 0; ii < 8; ++ii) {
                int i = t + 256 * ii, r = i >> 4, c2 = i & 15;
                pf2[ii] = *(const float2*)(x + ((long)b * C + c0 + r) * HW + nb + c2 * 2);
            }
            #pragma unroll
            for (int ii = 0; ii < 10; ++ii) {
                int i = t + 256 * ii, k = i >> 4, c2 = i & 15;
                if (k < KCLS) {
                    const u32* p = E32 + ((long)b * KCLS + k) * HW + nb + c2 * 2;
                    pw0[ii] = p[0]; pw1[ii] = p[1];
                } else { pw0[ii] = 0; pw1[ii] = 0; }
            }
        }
        tile_mma(sAh, sAl, sBh, sBl, acc, wm, wn, g, tid);
    }

    const long base = ((long)sp * BATCH + b) * KCLS;
    #pragma unroll
    for (int mi = 0; mi < 4; ++mi) {
        const int r0 = wm * 64 + mi * 16 + g;
        #pragma unroll
        for (int ni = 0; ni < 5; ++ni) {
            const int cb = wn * 40 + ni * 8 + tid * 2;
            if (cb < KCLS) {
                poolpart[(base + cb) * C + c0 + r0]     = acc[mi][ni][0];
                poolpart[(base + cb) * C + c0 + r0 + 8] = acc[mi][ni][2];
            }
            if (cb + 1 < KCLS) {
                poolpart[(base + cb + 1) * C + c0 + r0]     = acc[mi][ni][1];
                poolpart[(base + cb + 1) * C + c0 + r0 + 8] = acc[mi][ni][3];
            }
        }
    }
}

// ===========================================================================
// masks (HMMA, pipelined): D[n=128,k=160] = x^T·acls + pos_attn·G^T, then LN.
// ===========================================================================
__global__ __launch_bounds__(256) void k_masks_mma(
    const float* __restrict__ x, const u16* __restrict__ aclsh, const u16* __restrict__ aclsl,
    const u16* __restrict__ Gh, const u16* __restrict__ Gl,
    const u32* __restrict__ E32, const float* __restrict__ colinv,
    const float* __restrict__ gamma, const float* __restrict__ beta,
    float* __restrict__ out)
{
    __shared__ u32 sAh[128 * LDT], sAl[128 * LDT], sBh[KPAD * LDT], sBl[KPAD * LDT];
    __shared__ float ssum[128], ssq[128], civ[128];
    const int t = threadIdx.x;
    const int wid = t >> 5, lane = t & 31, g = lane >> 2, tid = lane & 3;
    const int wm = wid >> 2, wn = wid & 3;
    const int n0 = blockIdx.x * 128, b = blockIdx.y;
    if (t < 128) {
        ssum[t] = 0.f; ssq[t] = 0.f;
        civ[t] = colinv[(long)b * HW + n0 + t];
    }

    float acc[4][5][4] = {};
    const int n = t & 127, half = t >> 7;
    const float* xb = x + (long)b * C * HW + n0 + n;
    const u32* ah32 = (const u32*)(aclsh + (long)b * KPAD * C);
    const u32* al32 = (const u32*)(aclsl + (long)b * KPAD * C);
    const u32* gh32 = (const u32*)(Gh + (long)b * KPAD * KP2);
    const u32* gl32 = (const u32*)(Gl + (long)b * KPAD * KP2);

    float pxa[16];
    u32 pbh[10], pbl[10];
    #pragma unroll
    for (int j = 0; j < 8; ++j) {
        int c = (half * 8 + j) * 2;
        pxa[2 * j] = xb[(long)c * HW]; pxa[2 * j + 1] = xb[(long)(c + 1) * HW];
    }
    #pragma unroll
    for (int ii = 0; ii < 10; ++ii) {
        int i = t + 256 * ii, k = i >> 4, c2 = i & 15;
        if (k < KCLS) { pbh[ii] = ah32[k * (C / 2) + c2]; pbl[ii] = al32[k * (C / 2) + c2]; }
        else { pbh[ii] = 0; pbl[ii] = 0; }
    }

    // phase 1: reduction over c  (A = x^T, B = acls)
    for (int cc = 0; cc < C / KC; ++cc) {
        __syncthreads();
        #pragma unroll
        for (int j = 0; j < 8; ++j) {
            int c2 = half * 8 + j;
            u32 hv, lv;
            split2(pxa[2 * j], pxa[2 * j + 1], &hv, &lv);
            int ix = aidx(n, c2);
            sAh[ix] = hv; sAl[ix] = lv;
        }
        #pragma unroll
        for (int ii = 0; ii < 10; ++ii) {
            int i = t + 256 * ii, k = i >> 4, c2 = i & 15;
            sBh[k * LDT + c2] = pbh[ii]; sBl[k * LDT + c2] = pbl[ii];
        }
        __syncthreads();
        if (cc + 1 < C / KC) {
            #pragma unroll
            for (int j = 0; j < 8; ++j) {
                int c = (cc + 1) * KC + (half * 8 + j) * 2;
                pxa[2 * j] = xb[(long)c * HW]; pxa[2 * j + 1] = xb[(long)(c + 1) * HW];
            }
            #pragma unroll
            for (int ii = 0; ii < 10; ++ii) {
                int i = t + 256 * ii, k = i >> 4, c2 = i & 15;
                if (k < KCLS) {
                    pbh[ii] = ah32[k * (C / 2) + (cc + 1) * 16 + c2];
                    pbl[ii] = al32[k * (C / 2) + (cc + 1) * 16 + c2];
                } else { pbh[ii] = 0; pbl[ii] = 0; }
            }
        } else {
            // prefetch phase-2 chunk 0
            #pragma unroll
            for (int j = 0; j < 8; ++j) {
                int kq = (half * 8 + j) * 2;
                pxa[2 * j] = (kq < KCLS) ?
                    unpackE(E32[((long)b * KCLS + kq) * HW + n0 + n]) : 0.f;
                pxa[2 * j + 1] = (kq + 1 < KCLS) ?
                    unpackE(E32[((long)b * KCLS + kq + 1) * HW + n0 + n]) : 0.f;
            }
            #pragma unroll
            for (int ii = 0; ii < 10; ++ii) {
                int i = t + 256 * ii, k = i >> 4, c2 = i & 15;
                pbh[ii] = gh32[k * (KP2 / 2) + c2];
                pbl[ii] = gl32[k * (KP2 / 2) + c2];
            }
        }
        tile_mma(sAh, sAl, sBh, sBl, acc, wm, wn, g, tid);
    }
    // phase 2: reduction over k'  (A = pos_attn, B = G)
    const float ci = civ[n];
    for (int pc = 0; pc < KP2 / KC; ++pc) {
        __syncthreads();
        #pragma unroll
        for (int j = 0; j < 8; ++j) {
            int q2 = half * 8 + j;
            u32 hv, lv;
            split2(pxa[2 * j] * ci, pxa[2 * j + 1] * ci, &hv, &lv);
            int ix = aidx(n, q2);
            sAh[ix] = hv; sAl[ix] = lv;
        }
        #pragma unroll
        for (int ii = 0; ii < 10; ++ii) {
            int i = t + 256 * ii, k = i >> 4, c2 = i & 15;
            sBh[k * LDT + c2] = pbh[ii]; sBl[k * LDT + c2] = pbl[ii];
        }
        __syncthreads();
        if (pc + 1 < KP2 / KC) {
            #pragma unroll
            for (int j = 0; j < 8; ++j) {
                int kq = (pc + 1) * KC + (half * 8 + j) * 2;
                pxa[2 * j] = (kq < KCLS) ?
                    unpackE(E32[((long)b * KCLS + kq) * HW + n0 + n]) : 0.f;
                pxa[2 * j + 1] = (kq + 1 < KCLS) ?
                    unpackE(E32[((long)b * KCLS + kq + 1) * HW + n0 + n]) : 0.f;
            }
            #pragma unroll
            for (int ii = 0; ii < 10; ++ii) {
                int i = t + 256 * ii, k = i >> 4, c2 = i & 15;
                pbh[ii] = gh32[k * (KP2 / 2) + (pc + 1) * 16 + c2];
                pbl[ii] = gl32[k * (KP2 / 2) + (pc + 1) * 16 + c2];
            }
        }
        tile_mma(sAh, sAl, sBh, sBl, acc, wm, wn, g, tid);
    }

    // LayerNorm stats over k (<150) via smem atomics
    #pragma unroll
    for (int mi = 0; mi < 4; ++mi) {
        const int r0 = wm * 64 + mi * 16 + g;
        float s0 = 0.f, q0 = 0.f, s1 = 0.f, q1 = 0.f;
        #pragma unroll
        for (int ni = 0; ni < 5; ++ni) {
            const int cb = wn * 40 + ni * 8 + tid * 2;
            if (cb < KCLS) {
                float v = acc[mi][ni][0]; s0 += v; q0 += v * v;
                v = acc[mi][ni][2]; s1 += v; q1 += v * v;
            }
            if (cb + 1 < KCLS) {
                float v = acc[mi][ni][1]; s0 += v; q0 += v * v;
                v = acc[mi][ni][3]; s1 += v; q1 += v * v;
            }
        }
        atomicAdd(&ssum[r0], s0); atomicAdd(&ssq[r0], q0);
        atomicAdd(&ssum[r0 + 8], s1); atomicAdd(&ssq[r0 + 8], q1);
    }
    __syncthreads();
    #pragma unroll
    for (int mi = 0; mi < 4; ++mi) {
        const int r0 = wm * 64 + mi * 16 + g;
        const float mu0 = ssum[r0] * (1.f / KCLS);
        const float rs0 = rsqrtf(ssq[r0] * (1.f / KCLS) - mu0 * mu0 + 1e-5f);
        const float mu1 = ssum[r0 + 8] * (1.f / KCLS);
        const float rs1 = rsqrtf(ssq[r0 + 8] * (1.f / KCLS) - mu1 * mu1 + 1e-5f);
        #pragma unroll
        for (int ni = 0; ni < 5; ++ni) {
            const int cb = wn * 40 + ni * 8 + tid * 2;
            if (cb < KCLS) {
                float ga = gamma[cb], be = beta[cb];
                out[((long)b * KCLS + cb) * HW + n0 + r0] =
                    (acc[mi][ni][0] - mu0) * rs0 * ga + be;
                out[((long)b * KCLS + cb) * HW + n0 + r0 + 8] =
                    (acc[mi][ni][2] - mu1) * rs1 * ga + be;
            }
            if (cb + 1 < KCLS) {
                float ga = gamma[cb + 1], be = beta[cb + 1];
                out[((long)b * KCLS + cb + 1) * HW + n0 + r0] =
                    (acc[mi][ni][1] - mu0) * rs0 * ga + be;
                out[((long)b * KCLS + cb + 1) * HW + n0 + r0 + 8] =
                    (acc[mi][ni][3] - mu1) * rs1 * ga + be;
            }
        }
    }
}

// ===========================================================================
// SIMT small kernels
// ===========================================================================
__global__ void k_prep(const float* __restrict__ cls, u16* __restrict__ ch_, u16* __restrict__ cl_)
{
    int i = blockIdx.x * 256 + threadIdx.x;
    if (i < KPAD * C) {
        float v = (i < KCLS * C) ? cls[i] : 0.f;
        u32 u = __float_as_uint(v);
        float l = v - __uint_as_float(u & 0xFFFF0000u);
        ch_[i] = (u16)(u >> 16);
        cl_[i] = (u16)(__float_as_uint(l) >> 16);
    }
}

__global__ void k_rowred(const float* __restrict__ rowpart, float* __restrict__ rinv)
{
    int idx = blockIdx.x * 256 + threadIdx.x;
    if (idx < BATCH * KPAD) {
        const float* p = rowpart + (long)idx * (HW / 128);
        float s = 0.f;
        for (int i = 0; i < HW / 128; ++i) s += p[i];
        rinv[idx] = 1.f / s;
    }
}

__device__ __forceinline__ void sg_body(
    const float* __restrict__ A, int arow_valid, const float* __restrict__ W, int brow_valid,
    float acc[4][4], int t, float As[16][64], float Bs[16][64])
{
    const int tm = (t >> 4) * 4, tn = (t & 15) * 4;
    const int ar = t >> 2, ac = (t & 3) * 4;
    const int bc = t >> 2, bp = (t & 3) * 4;
    for (int p0 = 0; p0 < C; p0 += 16) {
        float4 av = make_float4(0.f, 0.f, 0.f, 0.f);
        if (ar < arow_valid) av = *(const float4*)&A[(long)ar * C + p0 + ac];
        As[ac + 0][ar] = av.x; As[ac + 1][ar] = av.y; As[ac + 2][ar] = av.z; As[ac + 3][ar] = av.w;
        float4 bv = make_float4(0.f, 0.f, 0.f, 0.f);
        if (bc < brow_valid) bv = *(const float4*)&W[(long)bc * C + p0 + bp];
        Bs[bp + 0][bc] = bv.x; Bs[bp + 1][bc] = bv.y; Bs[bp + 2][bc] = bv.z; Bs[bp + 3][bc] = bv.w;
        __syncthreads();
        #pragma unroll
        for (int kk = 0; kk < 16; ++kk) {
            float4 a4 = *(const float4*)&As[kk][tm];
            float4 b4 = *(const float4*)&Bs[kk][tn];
            float aa[4] = {a4.x, a4.y, a4.z, a4.w};
            float bb[4] = {b4.x, b4.y, b4.z, b4.w};
            #pragma unroll
            for (int i = 0; i < 4; ++i)
                #pragma unroll
                for (int j = 0; j < 4; ++j)
                    acc[i][j] = fmaf(aa[i], bb[j], acc[i][j]);
        }
        __syncthreads();
    }
}

__global__ __launch_bounds__(256) void k_clsWf(
    const float* __restrict__ cls, const float* __restrict__ W, float* __restrict__ outw)
{
    __shared__ float As[16][64], Bs[16][64];
    const int t = threadIdx.x, k0 = blockIdx.x * 64, c0 = blockIdx.y * 64;
    float acc[4][4] = {};
    int av = KCLS - k0; av = av > 64 ? 64 : (av > 0 ? av : 0);
    sg_body(cls + (long)k0 * C, av, W + (long)c0 * C, 64, acc, t, As, Bs);
    const int tm = (t >> 4) * 4, tn = (t & 15) * 4;
    #pragma unroll
    for (int i = 0; i < 4; ++i) {
        int k = k0 + tm + i;
        if (k < KCLS)
            *(float4*)&outw[(long)k * C + c0 + tn] =
                make_float4(acc[i][0], acc[i][1], acc[i][2], acc[i][3]);
    }
}

__global__ __launch_bounds__(256) void k_acls(
    const float* __restrict__ poolpart, const float* __restrict__ rinv,
    const float* __restrict__ W, const float* __restrict__ cls,
    float* __restrict__ outf, u16* __restrict__ outh, u16* __restrict__ outl)
{
    __shared__ float As[16][64], Bs[16][64];
    const int t = threadIdx.x;
    const int k0 = blockIdx.x * 64, c0 = blockIdx.y * 64, b = blockIdx.z;
    const int tm = (t >> 4) * 4, tn = (t & 15) * 4;
    const int ar = t >> 2, ac = (t & 3) * 4;
    const int bc = t >> 2, bp = (t & 3) * 4;
    float acc[4][4] = {};
    const int ka = k0 + ar;
    const float rv = (ka < KCLS) ? rinv[b * KPAD + ka] : 0.f;

    for (int p0 = 0; p0 < C; p0 += 16) {
        float4 av = make_float4(0.f, 0.f, 0.f, 0.f);
        if (ka < KCLS) {
            #pragma unroll
            for (int s = 0; s < NSPLIT; ++s) {
                float4 v = *(const float4*)
                    &poolpart[(((long)s * BATCH + b) * KCLS + ka) * C + p0 + ac];
                av.x += v.x; av.y += v.y; av.z += v.z; av.w += v.w;
            }
            av.x *= rv; av.y *= rv; av.z *= rv; av.w *= rv;
        }
        As[ac + 0][ar] = av.x; As[ac + 1][ar] = av.y; As[ac + 2][ar] = av.z; As[ac + 3][ar] = av.w;
        float4 bv = *(const float4*)&W[(long)(c0 + bc) * C + p0 + bp];
        Bs[bp + 0][bc] = bv.x; Bs[bp + 1][bc] = bv.y; Bs[bp + 2][bc] = bv.z; Bs[bp + 3][bc] = bv.w;
        __syncthreads();
        #pragma unroll
        for (int kk = 0; kk < 16; ++kk) {
            float4 a4 = *(const float4*)&As[kk][tm];
            float4 b4 = *(const float4*)&Bs[kk][tn];
            float aa[4] = {a4.x, a4.y, a4.z, a4.w};
            float bb[4] = {b4.x, b4.y, b4.z, b4.w};
            #pragma unroll
            for (int i = 0; i < 4; ++i)
                #pragma unroll
                for (int j = 0; j < 4; ++j)
                    acc[i][j] = fmaf(aa[i], bb[j], acc[i][j]);
        }
        __syncthreads();
    }
    #pragma unroll
    for (int i = 0; i < 4; ++i) {
        int k = k0 + tm + i;
        if (k < KCLS) {
            #pragma unroll
            for (int j = 0; j < 4; ++j) {
                float v = acc[i][j] + cls[(long)k * C + c0 + tn + j];
                outf[((long)b * KCLS + k) * C + c0 + tn + j] = v;
                long po = ((long)b * KPAD + k) * C + c0 + tn + j;
                u32 u = __float_as_uint(v);
                float l = v - __uint_as_float(u & 0xFFFF0000u);
                outh[po] = (u16)(u >> 16);
                outl[po] = (u16)(__float_as_uint(l) >> 16);
            }
        }
    }
}

__global__ __launch_bounds__(256) void k_G(
    const float* __restrict__ acls, const float* __restrict__ clsWf,
    u16* __restrict__ Gh, u16* __restrict__ Gl)
{
    __shared__ float As[16][64], Bs[16][64];
    const int t = threadIdx.x;
    const int k0 = blockIdx.x * 64, k20 = blockIdx.y * 64, b = blockIdx.z;
    float acc[4][4] = {};
    int av = KCLS - k0; av = av > 64 ? 64 : (av > 0 ? av : 0);
    int bv = KCLS - k20; bv = bv > 64 ? 64 : (bv > 0 ? bv : 0);
    sg_body(acls + ((long)b * KCLS + k0) * C, av, clsWf + (long)k20 * C, bv, acc, t, As, Bs);
    const int tm = (t >> 4) * 4, tn = (t & 15) * 4;
    #pragma unroll
    for (int i = 0; i < 4; ++i) {
        int k = k0 + tm + i;
        if (k < KPAD) {
            #pragma unroll
            for (int j = 0; j < 4; ++j) {
                float v = acc[i][j];
                long po = ((long)b * KPAD + k) * KP2 + k20 + tn + j;
                u32 u = __float_as_uint(v);
                float l = v - __uint_as_float(u & 0xFFFF0000u);
                Gh[po] = (u16)(u >> 16);
                Gl[po] = (u16)(__float_as_uint(l) >> 16);
            }
        }
    }
}

// ===========================================================================
extern "C" void kernel_launch(void* const* d_in, const int* in_sizes, int n_in,
                              void* d_out, int out_size)
{
    const float* x     = (const float*)d_in[0];
    const float* cls   = (const float*)d_in[1];
    const float* Wcls  = (const float*)d_in[2];
    const float* Wfeat = (const float*)d_in[3];
    const float* gamma = (const float*)d_in[4];
    const float* beta  = (const float*)d_in[5];
    float* out = (float*)d_out;

    u16 *clsh, *clsl, *aclsh, *aclsl, *Gh, *Gl;
    u32* E32;
    float *colinv, *rowpart, *rinv, *poolpart, *acls, *clsWf;
    cudaGetSymbolAddress((void**)&clsh,  g_clsh);
    cudaGetSymbolAddress((void**)&clsl,  g_clsl);
    cudaGetSymbolAddress((void**)&E32,   g_E32);
    cudaGetSymbolAddress((void**)&colinv, g_colinv);
    cudaGetSymbolAddress((void**)&rowpart, g_rowpart);
    cudaGetSymbolAddress((void**)&rinv,  g_rinv);
    cudaGetSymbolAddress((void**)&poolpart, g_poolpart);
    cudaGetSymbolAddress((void**)&acls,  g_acls);
    cudaGetSymbolAddress((void**)&aclsh, g_aclsh);
    cudaGetSymbolAddress((void**)&aclsl, g_aclsl);
    cudaGetSymbolAddress((void**)&clsWf, g_clsWf);
    cudaGetSymbolAddress((void**)&Gh,    g_Gh);
    cudaGetSymbolAddress((void**)&Gl,    g_Gl);

    k_prep<<<(KPAD * C + 255) / 256, 256>>>(cls, clsh, clsl);
    k_gemm1_mma<<<dim3(HW / 128, BATCH), 256>>>(x, clsh, clsl, E32, colinv, rowpart);
    k_rowred<<<(BATCH * KPAD + 255) / 256, 256>>>(rowpart, rinv);
    k_pool_mma<<<dim3(C / 128, NSPLIT, BATCH), 256>>>(x, E32, poolpart);
    k_clsWf<<<dim3(3, C / 64), 256>>>(cls, Wfeat, clsWf);
    k_acls<<<dim3(3, C / 64, BATCH), 256>>>(poolpart, rinv, Wcls, cls, acls, aclsh, aclsl);
    k_G<<<dim3(3, 3, BATCH), 256>>>(acls, clsWf, Gh, Gl);
    k_masks_mma<<<dim3(HW / 128, BATCH), 256>>>(
        x, aclsh, aclsl, Gh, Gl, E32, colinv, gamma, beta, out);
}

// round 8
// speedup vs baseline: 2.6788x; 1.0145x over previous
#include <cuda_runtime.h>
#include <stdint.h>

#define BATCH 8
#define C 512
#define HW 16384
#define KCLS 150
#define KPAD 160
#define KP2 192
#define NSPLIT 16
#define KC 32
#define LDT 20            // u32 row stride (conflict-free ldmatrix rows)
#define SA (128 * LDT)    // A tile u32s
#define SB (KPAD * LDT)   // B tile u32s
#define BUFSZ (2 * SA + 2 * SB)
#define SMEM_MMA (2 * BUFSZ * 4 + 2048)

typedef unsigned int u32;
typedef unsigned short u16;

// ---------------- scratch (device globals; no allocations) ----------------
__device__ u16  g_clsh[KPAD * C];
__device__ u16  g_clsl[KPAD * C];
__device__ u32  g_E32[(long)BATCH * KCLS * HW];  // packed: hi bf16 | lo bf16
__device__ float g_colinv[BATCH * HW];
__device__ float g_rowpart[(long)BATCH * KPAD * (HW / 128)];
__device__ float g_rinv[BATCH * KPAD];
__device__ float g_poolpart[(long)NSPLIT * BATCH * KCLS * C];
__device__ float g_acls[BATCH * KCLS * C];
__device__ u16  g_aclsh[BATCH * KPAD * C];
__device__ u16  g_aclsl[BATCH * KPAD * C];
__device__ float g_clsWf[KCLS * C];
__device__ u16  g_Gh[BATCH * KPAD * KP2];
__device__ u16  g_Gl[BATCH * KPAD * KP2];

// ---------------- helpers ----------------
__device__ __forceinline__ void split2(float v0, float v1, u32* hv, u32* lv) {
    u32 u0 = __float_as_uint(v0), u1 = __float_as_uint(v1);
    float l0 = v0 - __uint_as_float(u0 & 0xFFFF0000u);
    float l1 = v1 - __uint_as_float(u1 & 0xFFFF0000u);
    *hv = __byte_perm(u0, u1, 0x7632);
    *lv = __byte_perm(__float_as_uint(l0), __float_as_uint(l1), 0x7632);
}
__device__ __forceinline__ u32 packE(float e) {
    u32 u = __float_as_uint(e);
    float lo = e - __uint_as_float(u & 0xFFFF0000u);
    return (u >> 16) | (__float_as_uint(lo) & 0xFFFF0000u);
}
__device__ __forceinline__ float unpackE(u32 w) {
    return __uint_as_float((w & 0xFFFFu) << 16) + __uint_as_float(w & 0xFFFF0000u);
}
__device__ __forceinline__ void mma16816(float c[4], const u32 a[4], const u32 b[2]) {
    asm volatile(
        "mma.sync.aligned.m16n8k16.row.col.f32.bf16.bf16.f32 "
        "{%0,%1,%2,%3}, {%4,%5,%6,%7}, {%8,%9}, {%0,%1,%2,%3};"
        : "+f"(c[0]), "+f"(c[1]), "+f"(c[2]), "+f"(c[3])
        : "r"(a[0]), "r"(a[1]), "r"(a[2]), "r"(a[3]), "r"(b[0]), "r"(b[1]));
}
__device__ __forceinline__ void ldmat_x4(u32 r[4], const u32* p) {
    u32 a = (u32)__cvta_generic_to_shared(p);
    asm volatile("ldmatrix.sync.aligned.m8n8.x4.shared.b16 {%0,%1,%2,%3}, [%4];"
                 : "=r"(r[0]), "=r"(r[1]), "=r"(r[2]), "=r"(r[3]) : "r"(a));
}
__device__ __forceinline__ void ldmat_x2(u32 r[2], const u32* p) {
    u32 a = (u32)__cvta_generic_to_shared(p);
    asm volatile("ldmatrix.sync.aligned.m8n8.x2.shared.b16 {%0,%1}, [%2];"
                 : "=r"(r[0]), "=r"(r[1]) : "r"(a));
}

// CTA tile 128x160, one K-chunk of 32. Warp (wm,wn): rows [wm*64,+64), cols [wn*40,+40).
__device__ __forceinline__ void tile_mma(
    const u32* __restrict__ buf, float (*acc)[5][4], int wm, int wn, int lane)
{
    const u32* Ah = buf;
    const u32* Al = buf + SA;
    const u32* Bh = buf + 2 * SA;
    const u32* Bl = buf + 2 * SA + SB;
    const int arow = lane & 15, acol = (lane >> 4) << 2;
    const int brow = lane & 7,  bcol = ((lane >> 3) & 1) << 2;
    #pragma unroll
    for (int ks = 0; ks < 2; ++ks) {
        const int k2b = ks * 8;
        u32 ah[4][4], al[4][4];
        #pragma unroll
        for (int mi = 0; mi < 4; ++mi) {
            const int r = wm * 64 + mi * 16 + arow;
            ldmat_x4(ah[mi], Ah + r * LDT + k2b + acol);
            ldmat_x4(al[mi], Al + r * LDT + k2b + acol);
        }
        #pragma unroll
        for (int ni = 0; ni < 5; ++ni) {
            const int nr = wn * 40 + ni * 8 + brow;
            u32 bh[2], bl[2];
            ldmat_x2(bh, Bh + nr * LDT + k2b + bcol);
            ldmat_x2(bl, Bl + nr * LDT + k2b + bcol);
            #pragma unroll
            for (int mi = 0; mi < 4; ++mi) {
                mma16816(acc[mi][ni], ah[mi], bh);
                mma16816(acc[mi][ni], al[mi], bh);
                mma16816(acc[mi][ni], ah[mi], bl);
            }
        }
    }
}

// store helpers: A via uint4 (thread owns row n, cols half*8..+8), B scalar
__device__ __forceinline__ void storeA_vec(u32* buf, int n, int half,
                                           const float* pxa) {
    u32 hvs[8], lvs[8];
    #pragma unroll
    for (int j = 0; j < 8; ++j) split2(pxa[2 * j], pxa[2 * j + 1], &hvs[j], &lvs[j]);
    u32* a = buf + n * LDT + half * 8;
    *(uint4*)(a)          = make_uint4(hvs[0], hvs[1], hvs[2], hvs[3]);
    *(uint4*)(a + 4)      = make_uint4(hvs[4], hvs[5], hvs[6], hvs[7]);
    u32* b = buf + SA + n * LDT + half * 8;
    *(uint4*)(b)          = make_uint4(lvs[0], lvs[1], lvs[2], lvs[3]);
    *(uint4*)(b + 4)      = make_uint4(lvs[4], lvs[5], lvs[6], lvs[7]);
}
__device__ __forceinline__ void storeB_scalar(u32* buf, int t,
                                              const u32* pbh, const u32* pbl) {
    u32* Bh = buf + 2 * SA;
    u32* Bl = buf + 2 * SA + SB;
    #pragma unroll
    for (int ii = 0; ii < 10; ++ii) {
        int i = t + 256 * ii, k = i >> 4, c2 = i & 15;
        Bh[k * LDT + c2] = pbh[ii];
        Bl[k * LDT + c2] = pbl[ii];
    }
}

// ===========================================================================
// GEMM1: D[n=128,k=160] = x^T·cls ; E=exp(D), colinv, rowpart.
// ===========================================================================
__global__ __launch_bounds__(256) void k_gemm1_mma(
    const float* __restrict__ x, const u16* __restrict__ clsh, const u16* __restrict__ clsl,
    u32* __restrict__ E32, float* __restrict__ colinv, float* __restrict__ rowpart)
{
    extern __shared__ u32 sm[];
    float* srow  = (float*)(sm + 2 * BUFSZ);
    float* skrow = srow + 128;
    const int t = threadIdx.x;
    const int wid = t >> 5, lane = t & 31, g = lane >> 2, tid = lane & 3;
    const int wm = wid >> 2, wn = wid & 3;
    const int n0 = blockIdx.x * 128, b = blockIdx.y;
    if (t < 128) srow[t] = 0.f;
    if (t < KPAD) skrow[t] = 0.f;

    float acc[4][5][4] = {};
    const int n = t & 127, half = t >> 7;
    const float* xb = x + (long)b * C * HW + n0 + n;
    const u32* ch32 = (const u32*)clsh;
    const u32* cl32 = (const u32*)clsl;

    float pxa[16];
    u32 pbh[10], pbl[10];
    #pragma unroll
    for (int j = 0; j < 8; ++j) {
        int c = (half * 8 + j) * 2;
        pxa[2 * j] = xb[(long)c * HW]; pxa[2 * j + 1] = xb[(long)(c + 1) * HW];
    }
    #pragma unroll
    for (int ii = 0; ii < 10; ++ii) {
        int i = t + 256 * ii, k = i >> 4, c2 = i & 15;
        pbh[ii] = ch32[k * (C / 2) + c2];
        pbl[ii] = cl32[k * (C / 2) + c2];
    }
    storeA_vec(sm, n, half, pxa);
    storeB_scalar(sm, t, pbh, pbl);
    __syncthreads();

    #pragma unroll 1
    for (int cc = 0; cc < C / KC; ++cc) {
        if (cc + 1 < C / KC) {
            #pragma unroll
            for (int j = 0; j < 8; ++j) {
                int c = (cc + 1) * KC + (half * 8 + j) * 2;
                pxa[2 * j] = xb[(long)c * HW]; pxa[2 * j + 1] = xb[(long)(c + 1) * HW];
            }
            #pragma unroll
            for (int ii = 0; ii < 10; ++ii) {
                int i = t + 256 * ii, k = i >> 4, c2 = i & 15;
                pbh[ii] = ch32[k * (C / 2) + (cc + 1) * 16 + c2];
                pbl[ii] = cl32[k * (C / 2) + (cc + 1) * 16 + c2];
            }
        }
        tile_mma(sm + (cc & 1) * BUFSZ, acc, wm, wn, lane);
        if (cc + 1 < C / KC) {
            u32* nb = sm + ((cc + 1) & 1) * BUFSZ;
            storeA_vec(nb, n, half, pxa);
            storeB_scalar(nb, t, pbh, pbl);
            __syncthreads();
        }
    }

    #pragma unroll
    for (int mi = 0; mi < 4; ++mi) {
        const int r0 = wm * 64 + mi * 16 + g;
        float s0 = 0.f, s1 = 0.f;
        #pragma unroll
        for (int ni = 0; ni < 5; ++ni) {
            const int cb = wn * 40 + ni * 8 + tid * 2;
            float e0 = __expf(acc[mi][ni][0]);
            float e1 = __expf(acc[mi][ni][1]);
            float e2 = __expf(acc[mi][ni][2]);
            float e3 = __expf(acc[mi][ni][3]);
            float vk0 = 0.f, vk1 = 0.f;
            if (cb < KCLS) {
                E32[((long)b * KCLS + cb) * HW + n0 + r0]     = packE(e0);
                E32[((long)b * KCLS + cb) * HW + n0 + r0 + 8] = packE(e2);
                s0 += e0; s1 += e2; vk0 = e0 + e2;
            }
            if (cb + 1 < KCLS) {
                E32[((long)b * KCLS + cb + 1) * HW + n0 + r0]     = packE(e1);
                E32[((long)b * KCLS + cb + 1) * HW + n0 + r0 + 8] = packE(e3);
                s0 += e1; s1 += e3; vk1 = e1 + e3;
            }
            vk0 += __shfl_xor_sync(0xFFFFFFFFu, vk0, 4);
            vk0 += __shfl_xor_sync(0xFFFFFFFFu, vk0, 8);
            vk0 += __shfl_xor_sync(0xFFFFFFFFu, vk0, 16);
            vk1 += __shfl_xor_sync(0xFFFFFFFFu, vk1, 4);
            vk1 += __shfl_xor_sync(0xFFFFFFFFu, vk1, 8);
            vk1 += __shfl_xor_sync(0xFFFFFFFFu, vk1, 16);
            if (g == 0 && cb < KCLS) {
                atomicAdd(&skrow[cb], vk0);
                if (cb + 1 < KCLS) atomicAdd(&skrow[cb + 1], vk1);
            }
        }
        atomicAdd(&srow[r0], s0);
        atomicAdd(&srow[r0 + 8], s1);
    }
    __syncthreads();
    if (t < 128) colinv[(long)b * HW + n0 + t] = 1.f / srow[t];
    if (t < KPAD)
        rowpart[((long)b * KPAD + t) * (HW / 128) + blockIdx.x] = skrow[t];
}

// ===========================================================================
// pool: D[c=128,k=160] = sum_n x[c,n]*E[k,n]  (split-K over n)
// ===========================================================================
__global__ __launch_bounds__(256) void k_pool_mma(
    const float* __restrict__ x, const u32* __restrict__ E32, float* __restrict__ poolpart)
{
    extern __shared__ u32 sm[];
    const int t = threadIdx.x;
    const int wid = t >> 5, lane = t & 31, g = lane >> 2, tid = lane & 3;
    const int wm = wid >> 2, wn = wid & 3;
    const int c0 = blockIdx.x * 128, sp = blockIdx.y, b = blockIdx.z;
    const int nbase = sp * (HW / NSPLIT);
    const int NCH = (HW / NSPLIT) / KC;
    float acc[4][5][4] = {};

    float2 pf2[8];
    u32 pw0[10], pw1[10];
    #pragma unroll
    for (int ii = 0; ii < 8; ++ii) {
        int i = t + 256 * ii, r = i >> 4, c2 = i & 15;
        pf2[ii] = *(const float2*)(x + ((long)b * C + c0 + r) * HW + nbase + c2 * 2);
    }
    #pragma unroll
    for (int ii = 0; ii < 10; ++ii) {
        int i = t + 256 * ii, k = i >> 4, c2 = i & 15;
        if (k < KCLS) {
            const u32* p = E32 + ((long)b * KCLS + k) * HW + nbase + c2 * 2;
            pw0[ii] = p[0]; pw1[ii] = p[1];
        } else { pw0[ii] = 0; pw1[ii] = 0; }
    }
    // store chunk 0
    {
        u32* Ah = sm; u32* Al = sm + SA; u32* Bh = sm + 2 * SA; u32* Bl = Bh + SB;
        #pragma unroll
        for (int ii = 0; ii < 8; ++ii) {
            int i = t + 256 * ii, r = i >> 4, c2 = i & 15;
            u32 hv, lv; split2(pf2[ii].x, pf2[ii].y, &hv, &lv);
            Ah[r * LDT + c2] = hv; Al[r * LDT + c2] = lv;
        }
        #pragma unroll
        for (int ii = 0; ii < 10; ++ii) {
            int i = t + 256 * ii, k = i >> 4, c2 = i & 15;
            Bh[k * LDT + c2] = __byte_perm(pw0[ii], pw1[ii], 0x5410);
            Bl[k * LDT + c2] = __byte_perm(pw0[ii], pw1[ii], 0x7632);
        }
    }
    __syncthreads();

    #pragma unroll 1
    for (int cc = 0; cc < NCH; ++cc) {
        if (cc + 1 < NCH) {
            const int nb = nbase + (cc + 1) * KC;
            #pragma unroll
            for (int ii = 0; ii < 8; ++ii) {
                int i = t + 256 * ii, r = i >> 4, c2 = i & 15;
                pf2[ii] = *(const float2*)(x + ((long)b * C + c0 + r) * HW + nb + c2 * 2);
            }
            #pragma unroll
            for (int ii = 0; ii < 10; ++ii) {
                int i = t + 256 * ii, k = i >> 4, c2 = i & 15;
                if (k < KCLS) {
                    const u32* p = E32 + ((long)b * KCLS + k) * HW + nb + c2 * 2;
                    pw0[ii] = p[0]; pw1[ii] = p[1];
                } else { pw0[ii] = 0; pw1[ii] = 0; }
            }
        }
        tile_mma(sm + (cc & 1) * BUFSZ, acc, wm, wn, lane);
        if (cc + 1 < NCH) {
            u32* buf = sm + ((cc + 1) & 1) * BUFSZ;
            u32* Ah = buf; u32* Al = buf + SA; u32* Bh = buf + 2 * SA; u32* Bl = Bh + SB;
            #pragma unroll
            for (int ii = 0; ii < 8; ++ii) {
                int i = t + 256 * ii, r = i >> 4, c2 = i & 15;
                u32 hv, lv; split2(pf2[ii].x, pf2[ii].y, &hv, &lv);
                Ah[r * LDT + c2] = hv; Al[r * LDT + c2] = lv;
            }
            #pragma unroll
            for (int ii = 0; ii < 10; ++ii) {
                int i = t + 256 * ii, k = i >> 4, c2 = i & 15;
                Bh[k * LDT + c2] = __byte_perm(pw0[ii], pw1[ii], 0x5410);
                Bl[k * LDT + c2] = __byte_perm(pw0[ii], pw1[ii], 0x7632);
            }
            __syncthreads();
        }
    }

    const long base = ((long)sp * BATCH + b) * KCLS;
    #pragma unroll
    for (int mi = 0; mi < 4; ++mi) {
        const int r0 = wm * 64 + mi * 16 + g;
        #pragma unroll
        for (int ni = 0; ni < 5; ++ni) {
            const int cb = wn * 40 + ni * 8 + tid * 2;
            if (cb < KCLS) {
                poolpart[(base + cb) * C + c0 + r0]     = acc[mi][ni][0];
                poolpart[(base + cb) * C + c0 + r0 + 8] = acc[mi][ni][2];
            }
            if (cb + 1 < KCLS) {
                poolpart[(base + cb + 1) * C + c0 + r0]     = acc[mi][ni][1];
                poolpart[(base + cb + 1) * C + c0 + r0 + 8] = acc[mi][ni][3];
            }
        }
    }
}

// ===========================================================================
// masks: D[n=128,k=160] = x^T·acls + pos_attn·G^T over 14 chunks, then LN.
// ===========================================================================
__global__ __launch_bounds__(256) void k_masks_mma(
    const float* __restrict__ x, const u16* __restrict__ aclsh, const u16* __restrict__ aclsl,
    const u16* __restrict__ Gh, const u16* __restrict__ Gl,
    const u32* __restrict__ E32, const float* __restrict__ colinv,
    const float* __restrict__ gamma, const float* __restrict__ beta,
    float* __restrict__ out)
{
    extern __shared__ u32 sm[];
    float* ssum = (float*)(sm + 2 * BUFSZ);
    float* ssq  = ssum + 128;
    float* civ  = ssq + 128;
    const int t = threadIdx.x;
    const int wid = t >> 5, lane = t & 31, g = lane >> 2, tid = lane & 3;
    const int wm = wid >> 2, wn = wid & 3;
    const int n0 = blockIdx.x * 128, b = blockIdx.y;
    if (t < 128) {
        ssum[t] = 0.f; ssq[t] = 0.f;
        civ[t] = colinv[(long)b * HW + n0 + t];
    }

    float acc[4][5][4] = {};
    const int n = t & 127, half = t >> 7;
    const float* xb = x + (long)b * C * HW + n0 + n;
    const u32* ah32 = (const u32*)(aclsh + (long)b * KPAD * C);
    const u32* al32 = (const u32*)(aclsl + (long)b * KPAD * C);
    const u32* gh32 = (const u32*)(Gh + (long)b * KPAD * KP2);
    const u32* gl32 = (const u32*)(Gl + (long)b * KPAD * KP2);
    const int NCH1 = C / KC;          // 16
    const int NCH  = NCH1 + KP2 / KC; // 22... (C/KC=16? C=512,KC=32 -> 16; KP2/KC=6 -> 22)

    float pxa[16];
    u32 pbh[10], pbl[10];
    // load chunk 0 (phase 1)
    #pragma unroll
    for (int j = 0; j < 8; ++j) {
        int c = (half * 8 + j) * 2;
        pxa[2 * j] = xb[(long)c * HW]; pxa[2 * j + 1] = xb[(long)(c + 1) * HW];
    }
    #pragma unroll
    for (int ii = 0; ii < 10; ++ii) {
        int i = t + 256 * ii, k = i >> 4, c2 = i & 15;
        if (k < KCLS) { pbh[ii] = ah32[k * (C / 2) + c2]; pbl[ii] = al32[k * (C / 2) + c2]; }
        else { pbh[ii] = 0; pbl[ii] = 0; }
    }
    storeA_vec(sm, n, half, pxa);
    storeB_scalar(sm, t, pbh, pbl);
    __syncthreads();
    const float ci = civ[n];

    #pragma unroll 1
    for (int j = 0; j < NCH; ++j) {
        const int jn = j + 1;
        if (jn < NCH) {
            if (jn < NCH1) {
                #pragma unroll
                for (int jj = 0; jj < 8; ++jj) {
                    int c = jn * KC + (half * 8 + jj) * 2;
                    pxa[2 * jj] = xb[(long)c * HW];
                    pxa[2 * jj + 1] = xb[(long)(c + 1) * HW];
                }
                #pragma unroll
                for (int ii = 0; ii < 10; ++ii) {
                    int i = t + 256 * ii, k = i >> 4, c2 = i & 15;
                    if (k < KCLS) {
                        pbh[ii] = ah32[k * (C / 2) + jn * 16 + c2];
                        pbl[ii] = al32[k * (C / 2) + jn * 16 + c2];
                    } else { pbh[ii] = 0; pbl[ii] = 0; }
                }
            } else {
                const int pc = jn - NCH1;
                #pragma unroll
                for (int jj = 0; jj < 8; ++jj) {
                    int kq = pc * KC + (half * 8 + jj) * 2;
                    pxa[2 * jj] = (kq < KCLS) ?
                        unpackE(E32[((long)b * KCLS + kq) * HW + n0 + n]) * ci : 0.f;
                    pxa[2 * jj + 1] = (kq + 1 < KCLS) ?
                        unpackE(E32[((long)b * KCLS + kq + 1) * HW + n0 + n]) * ci : 0.f;
                }
                #pragma unroll
                for (int ii = 0; ii < 10; ++ii) {
                    int i = t + 256 * ii, k = i >> 4, c2 = i & 15;
                    pbh[ii] = gh32[k * (KP2 / 2) + pc * 16 + c2];
                    pbl[ii] = gl32[k * (KP2 / 2) + pc * 16 + c2];
                }
            }
        }
        tile_mma(sm + (j & 1) * BUFSZ, acc, wm, wn, lane);
        if (jn < NCH) {
            u32* nb = sm + (jn & 1) * BUFSZ;
            storeA_vec(nb, n, half, pxa);
            storeB_scalar(nb, t, pbh, pbl);
            __syncthreads();
        }
    }

    // LayerNorm over k (<150)
    #pragma unroll
    for (int mi = 0; mi < 4; ++mi) {
        const int r0 = wm * 64 + mi * 16 + g;
        float s0 = 0.f, q0 = 0.f, s1 = 0.f, q1 = 0.f;
        #pragma unroll
        for (int ni = 0; ni < 5; ++ni) {
            const int cb = wn * 40 + ni * 8 + tid * 2;
            if (cb < KCLS) {
                float v = acc[mi][ni][0]; s0 += v; q0 += v * v;
                v = acc[mi][ni][2]; s1 += v; q1 += v * v;
            }
            if (cb + 1 < KCLS) {
                float v = acc[mi][ni][1]; s0 += v; q0 += v * v;
                v = acc[mi][ni][3]; s1 += v; q1 += v * v;
            }
        }
        atomicAdd(&ssum[r0], s0); atomicAdd(&ssq[r0], q0);
        atomicAdd(&ssum[r0 + 8], s1); atomicAdd(&ssq[r0 + 8], q1);
    }
    __syncthreads();
    #pragma unroll
    for (int mi = 0; mi < 4; ++mi) {
        const int r0 = wm * 64 + mi * 16 + g;
        const float mu0 = ssum[r0] * (1.f / KCLS);
        const float rs0 = rsqrtf(ssq[r0] * (1.f / KCLS) - mu0 * mu0 + 1e-5f);
        const float mu1 = ssum[r0 + 8] * (1.f / KCLS);
        const float rs1 = rsqrtf(ssq[r0 + 8] * (1.f / KCLS) - mu1 * mu1 + 1e-5f);
        #pragma unroll
        for (int ni = 0; ni < 5; ++ni) {
            const int cb = wn * 40 + ni * 8 + tid * 2;
            if (cb < KCLS) {
                float ga = gamma[cb], be = beta[cb];
                out[((long)b * KCLS + cb) * HW + n0 + r0] =
                    (acc[mi][ni][0] - mu0) * rs0 * ga + be;
                out[((long)b * KCLS + cb) * HW + n0 + r0 + 8] =
                    (acc[mi][ni][2] - mu1) * rs1 * ga + be;
            }
            if (cb + 1 < KCLS) {
                float ga = gamma[cb + 1], be = beta[cb + 1];
                out[((long)b * KCLS + cb + 1) * HW + n0 + r0] =
                    (acc[mi][ni][1] - mu0) * rs0 * ga + be;
                out[((long)b * KCLS + cb + 1) * HW + n0 + r0 + 8] =
                    (acc[mi][ni][3] - mu1) * rs1 * ga + be;
            }
        }
    }
}

// ===========================================================================
// SIMT small kernels (unchanged)
// ===========================================================================
__global__ void k_prep(const float* __restrict__ cls, u16* __restrict__ ch_, u16* __restrict__ cl_)
{
    int i = blockIdx.x * 256 + threadIdx.x;
    if (i < KPAD * C) {
        float v = (i < KCLS * C) ? cls[i] : 0.f;
        u32 u = __float_as_uint(v);
        float l = v - __uint_as_float(u & 0xFFFF0000u);
        ch_[i] = (u16)(u >> 16);
        cl_[i] = (u16)(__float_as_uint(l) >> 16);
    }
}

__global__ void k_rowred(const float* __restrict__ rowpart, float* __restrict__ rinv)
{
    int idx = blockIdx.x * 256 + threadIdx.x;
    if (idx < BATCH * KPAD) {
        const float* p = rowpart + (long)idx * (HW / 128);
        float s = 0.f;
        for (int i = 0; i < HW / 128; ++i) s += p[i];
        rinv[idx] = 1.f / s;
    }
}

__device__ __forceinline__ void sg_body(
    const float* __restrict__ A, int arow_valid, const float* __restrict__ W, int brow_valid,
    float acc[4][4], int t, float As[16][64], float Bs[16][64])
{
    const int tm = (t >> 4) * 4, tn = (t & 15) * 4;
    const int ar = t >> 2, ac = (t & 3) * 4;
    const int bc = t >> 2, bp = (t & 3) * 4;
    for (int p0 = 0; p0 < C; p0 += 16) {
        float4 av = make_float4(0.f, 0.f, 0.f, 0.f);
        if (ar < arow_valid) av = *(const float4*)&A[(long)ar * C + p0 + ac];
        As[ac + 0][ar] = av.x; As[ac + 1][ar] = av.y; As[ac + 2][ar] = av.z; As[ac + 3][ar] = av.w;
        float4 bv = make_float4(0.f, 0.f, 0.f, 0.f);
        if (bc < brow_valid) bv = *(const float4*)&W[(long)bc * C + p0 + bp];
        Bs[bp + 0][bc] = bv.x; Bs[bp + 1][bc] = bv.y; Bs[bp + 2][bc] = bv.z; Bs[bp + 3][bc] = bv.w;
        __syncthreads();
        #pragma unroll
        for (int kk = 0; kk < 16; ++kk) {
            float4 a4 = *(const float4*)&As[kk][tm];
            float4 b4 = *(const float4*)&Bs[kk][tn];
            float aa[4] = {a4.x, a4.y, a4.z, a4.w};
            float bb[4] = {b4.x, b4.y, b4.z, b4.w};
            #pragma unroll
            for (int i = 0; i < 4; ++i)
                #pragma unroll
                for (int j = 0; j < 4; ++j)
                    acc[i][j] = fmaf(aa[i], bb[j], acc[i][j]);
        }
        __syncthreads();
    }
}

__global__ __launch_bounds__(256) void k_clsWf(
    const float* __restrict__ cls, const float* __restrict__ W, float* __restrict__ outw)
{
    __shared__ float As[16][64], Bs[16][64];
    const int t = threadIdx.x, k0 = blockIdx.x * 64, c0 = blockIdx.y * 64;
    float acc[4][4] = {};
    int av = KCLS - k0; av = av > 64 ? 64 : (av > 0 ? av : 0);
    sg_body(cls + (long)k0 * C, av, W + (long)c0 * C, 64, acc, t, As, Bs);
    const int tm = (t >> 4) * 4, tn = (t & 15) * 4;
    #pragma unroll
    for (int i = 0; i < 4; ++i) {
        int k = k0 + tm + i;
        if (k < KCLS)
            *(float4*)&outw[(long)k * C + c0 + tn] =
                make_float4(acc[i][0], acc[i][1], acc[i][2], acc[i][3]);
    }
}

__global__ __launch_bounds__(256) void k_acls(
    const float* __restrict__ poolpart, const float* __restrict__ rinv,
    const float* __restrict__ W, const float* __restrict__ cls,
    float* __restrict__ outf, u16* __restrict__ outh, u16* __restrict__ outl)
{
    __shared__ float As[16][64], Bs[16][64];
    const int t = threadIdx.x;
    const int k0 = blockIdx.x * 64, c0 = blockIdx.y * 64, b = blockIdx.z;
    const int tm = (t >> 4) * 4, tn = (t & 15) * 4;
    const int ar = t >> 2, ac = (t & 3) * 4;
    const int bc = t >> 2, bp = (t & 3) * 4;
    float acc[4][4] = {};
    const int ka = k0 + ar;
    const float rv = (ka < KCLS) ? rinv[b * KPAD + ka] : 0.f;

    for (int p0 = 0; p0 < C; p0 += 16) {
        float4 av = make_float4(0.f, 0.f, 0.f, 0.f);
        if (ka < KCLS) {
            #pragma unroll
            for (int s = 0; s < NSPLIT; ++s) {
                float4 v = *(const float4*)
                    &poolpart[(((long)s * BATCH + b) * KCLS + ka) * C + p0 + ac];
                av.x += v.x; av.y += v.y; av.z += v.z; av.w += v.w;
            }
            av.x *= rv; av.y *= rv; av.z *= rv; av.w *= rv;
        }
        As[ac + 0][ar] = av.x; As[ac + 1][ar] = av.y; As[ac + 2][ar] = av.z; As[ac + 3][ar] = av.w;
        float4 bv = *(const float4*)&W[(long)(c0 + bc) * C + p0 + bp];
        Bs[bp + 0][bc] = bv.x; Bs[bp + 1][bc] = bv.y; Bs[bp + 2][bc] = bv.z; Bs[bp + 3][bc] = bv.w;
        __syncthreads();
        #pragma unroll
        for (int kk = 0; kk < 16; ++kk) {
            float4 a4 = *(const float4*)&As[kk][tm];
            float4 b4 = *(const float4*)&Bs[kk][tn];
            float aa[4] = {a4.x, a4.y, a4.z, a4.w};
            float bb[4] = {b4.x, b4.y, b4.z, b4.w};
            #pragma unroll
            for (int i = 0; i < 4; ++i)
                #pragma unroll
                for (int j = 0; j < 4; ++j)
                    acc[i][j] = fmaf(aa[i], bb[j], acc[i][j]);
        }
        __syncthreads();
    }
    #pragma unroll
    for (int i = 0; i < 4; ++i) {
        int k = k0 + tm + i;
        if (k < KCLS) {
            #pragma unroll
            for (int j = 0; j < 4; ++j) {
                float v = acc[i][j] + cls[(long)k * C + c0 + tn + j];
                outf[((long)b * KCLS + k) * C + c0 + tn + j] = v;
                long po = ((long)b * KPAD + k) * C + c0 + tn + j;
                u32 u = __float_as_uint(v);
                float l = v - __uint_as_float(u & 0xFFFF0000u);
                outh[po] = (u16)(u >> 16);
                outl[po] = (u16)(__float_as_uint(l) >> 16);
            }
        }
    }
}

__global__ __launch_bounds__(256) void k_G(
    const float* __restrict__ acls, const float* __restrict__ clsWf,
    u16* __restrict__ Gh, u16* __restrict__ Gl)
{
    __shared__ float As[16][64], Bs[16][64];
    const int t = threadIdx.x;
    const int k0 = blockIdx.x * 64, k20 = blockIdx.y * 64, b = blockIdx.z;
    float acc[4][4] = {};
    int av = KCLS - k0; av = av > 64 ? 64 : (av > 0 ? av : 0);
    int bv = KCLS - k20; bv = bv > 64 ? 64 : (bv > 0 ? bv : 0);
    sg_body(acls + ((long)b * KCLS + k0) * C, av, clsWf + (long)k20 * C, bv, acc, t, As, Bs);
    const int tm = (t >> 4) * 4, tn = (t & 15) * 4;
    #pragma unroll
    for (int i = 0; i < 4; ++i) {
        int k = k0 + tm + i;
        if (k < KPAD) {
            #pragma unroll
            for (int j = 0; j < 4; ++j) {
                float v = acc[i][j];
                long po = ((long)b * KPAD + k) * KP2 + k20 + tn + j;
                u32 u = __float_as_uint(v);
                float l = v - __uint_as_float(u & 0xFFFF0000u);
                Gh[po] = (u16)(u >> 16);
                Gl[po] = (u16)(__float_as_uint(l) >> 16);
            }
        }
    }
}

// ===========================================================================
extern "C" void kernel_launch(void* const* d_in, const int* in_sizes, int n_in,
                              void* d_out, int out_size)
{
    const float* x     = (const float*)d_in[0];
    const float* cls   = (const float*)d_in[1];
    const float* Wcls  = (const float*)d_in[2];
    const float* Wfeat = (const float*)d_in[3];
    const float* gamma = (const float*)d_in[4];
    const float* beta  = (const float*)d_in[5];
    float* out = (float*)d_out;

    u16 *clsh, *clsl, *aclsh, *aclsl, *Gh, *Gl;
    u32* E32;
    float *colinv, *rowpart, *rinv, *poolpart, *acls, *clsWf;
    cudaGetSymbolAddress((void**)&clsh,  g_clsh);
    cudaGetSymbolAddress((void**)&clsl,  g_clsl);
    cudaGetSymbolAddress((void**)&E32,   g_E32);
    cudaGetSymbolAddress((void**)&colinv, g_colinv);
    cudaGetSymbolAddress((void**)&rowpart, g_rowpart);
    cudaGetSymbolAddress((void**)&rinv,  g_rinv);
    cudaGetSymbolAddress((void**)&poolpart, g_poolpart);
    cudaGetSymbolAddress((void**)&acls,  g_acls);
    cudaGetSymbolAddress((void**)&aclsh, g_aclsh);
    cudaGetSymbolAddress((void**)&aclsl, g_aclsl);
    cudaGetSymbolAddress((void**)&clsWf, g_clsWf);
    cudaGetSymbolAddress((void**)&Gh,    g_Gh);
    cudaGetSymbolAddress((void**)&Gl,    g_Gl);

    cudaFuncSetAttribute(k_gemm1_mma, cudaFuncAttributeMaxDynamicSharedMemorySize, SMEM_MMA);
    cudaFuncSetAttribute(k_pool_mma,  cudaFuncAttributeMaxDynamicSharedMemorySize, SMEM_MMA);
    cudaFuncSetAttribute(k_masks_mma, cudaFuncAttributeMaxDynamicSharedMemorySize, SMEM_MMA);

    k_prep<<<(KPAD * C + 255) / 256, 256>>>(cls, clsh, clsl);
    k_gemm1_mma<<<dim3(HW / 128, BATCH), 256, SMEM_MMA>>>(x, clsh, clsl, E32, colinv, rowpart);
    k_rowred<<<(BATCH * KPAD + 255) / 256, 256>>>(rowpart, rinv);
    k_pool_mma<<<dim3(C / 128, NSPLIT, BATCH), 256, SMEM_MMA>>>(x, E32, poolpart);
    k_clsWf<<<dim3(3, C / 64), 256>>>(cls, Wfeat, clsWf);
    k_acls<<<dim3(3, C / 64, BATCH), 256>>>(poolpart, rinv, Wcls, cls, acls, aclsh, aclsl);
    k_G<<<dim3(3, 3, BATCH), 256>>>(acls, clsWf, Gh, Gl);
    k_masks_mma<<<dim3(HW / 128, BATCH), 256, SMEM_MMA>>>(
        x, aclsh, aclsl, Gh, Gl, E32, colinv, gamma, beta, out);
}

// round 9
// speedup vs baseline: 3.1083x; 1.1603x over previous
#include <cuda_runtime.h>
#include <stdint.h>

#define BATCH 8
#define C 512
#define HW 16384
#define KCLS 150
#define KPAD 160
#define KP2 192
#define NSPLIT 16
#define KC 32
#define LDT 20             // u32 row stride, non-trans tiles
#define LDTT 68            // u32 row stride, trans (K-major) A tiles
#define SA (128 * LDT)
#define SB (KPAD * LDT)
#define SAT (32 * LDTT)
#define BUF_N (2 * SA + 2 * SB)     // gemm1 / pool buffer (u32)
#define BUF_T (2 * SAT + 2 * SB)    // masks buffer (u32)
#define SMEM_N (2 * BUF_N * 4 + 2048)
#define SMEM_T (2 * BUF_T * 4 + 2048)

typedef unsigned int u32;
typedef unsigned short u16;

// ---------------- scratch (device globals; no allocations) ----------------
__device__ u16  g_clsh[KPAD * C];
__device__ u16  g_clsl[KPAD * C];
__device__ u16  g_xh[(long)BATCH * C * HW];
__device__ u16  g_xl[(long)BATCH * C * HW];
__device__ u16  g_Eh[(long)BATCH * KCLS * HW];
__device__ u16  g_El[(long)BATCH * KCLS * HW];
__device__ float g_colinv[BATCH * HW];
__device__ float g_rowpart[(long)BATCH * KPAD * (HW / 128)];
__device__ float g_rinv[BATCH * KPAD];
__device__ float g_poolpart[(long)NSPLIT * BATCH * KCLS * C];
__device__ float g_acls[BATCH * KCLS * C];
__device__ u16  g_aclsh[BATCH * KPAD * C];
__device__ u16  g_aclsl[BATCH * KPAD * C];
__device__ float g_clsWf[KCLS * C];
__device__ u16  g_Gh[BATCH * KPAD * KP2];
__device__ u16  g_Gl[BATCH * KPAD * KP2];

// ---------------- helpers ----------------
__device__ __forceinline__ void split2(float v0, float v1, u32* hv, u32* lv) {
    u32 u0 = __float_as_uint(v0), u1 = __float_as_uint(v1);
    float l0 = v0 - __uint_as_float(u0 & 0xFFFF0000u);
    float l1 = v1 - __uint_as_float(u1 & 0xFFFF0000u);
    *hv = __byte_perm(u0, u1, 0x7632);
    *lv = __byte_perm(__float_as_uint(l0), __float_as_uint(l1), 0x7632);
}
__device__ __forceinline__ void mma16816(float c[4], const u32 a[4], const u32 b[2]) {
    asm volatile(
        "mma.sync.aligned.m16n8k16.row.col.f32.bf16.bf16.f32 "
        "{%0,%1,%2,%3}, {%4,%5,%6,%7}, {%8,%9}, {%0,%1,%2,%3};"
        : "+f"(c[0]), "+f"(c[1]), "+f"(c[2]), "+f"(c[3])
        : "r"(a[0]), "r"(a[1]), "r"(a[2]), "r"(a[3]), "r"(b[0]), "r"(b[1]));
}
__device__ __forceinline__ void ldmat_x4(u32 r[4], const void* p) {
    u32 a = (u32)__cvta_generic_to_shared(p);
    asm volatile("ldmatrix.sync.aligned.m8n8.x4.shared.b16 {%0,%1,%2,%3}, [%4];"
                 : "=r"(r[0]), "=r"(r[1]), "=r"(r[2]), "=r"(r[3]) : "r"(a));
}
__device__ __forceinline__ void ldmat_x4t(u32 r[4], const void* p) {
    u32 a = (u32)__cvta_generic_to_shared(p);
    asm volatile("ldmatrix.sync.aligned.m8n8.x4.trans.shared.b16 {%0,%1,%2,%3}, [%4];"
                 : "=r"(r[0]), "=r"(r[1]), "=r"(r[2]), "=r"(r[3]) : "r"(a));
}
__device__ __forceinline__ void ldmat_x2(u32 r[2], const void* p) {
    u32 a = (u32)__cvta_generic_to_shared(p);
    asm volatile("ldmatrix.sync.aligned.m8n8.x2.shared.b16 {%0,%1}, [%2];"
                 : "=r"(r[0]), "=r"(r[1]) : "r"(a));
}
__device__ __forceinline__ void cpa16(void* dst, const void* src, u32 srcsz) {
    u32 d = (u32)__cvta_generic_to_shared(dst);
    asm volatile("cp.async.cg.shared.global [%0], [%1], 16, %2;"
                 :: "r"(d), "l"(src), "r"(srcsz) : "memory");
}
#define CP_COMMIT() asm volatile("cp.async.commit_group;" ::: "memory")
#define CP_WAIT0()  asm volatile("cp.async.wait_group 0;" ::: "memory")

// ---- MMA cores -------------------------------------------------------------
// non-trans: A smem [M=128 rows][K u32-pairs], B smem [N=160 rows][K]
__device__ __forceinline__ void tile_mma(
    const u32* Ah, const u32* Al, const u32* Bh, const u32* Bl,
    float (*acc)[5][4], int wm, int wn, int lane)
{
    const int arow = lane & 15, acol = (lane >> 4) << 2;
    const int brow = lane & 7,  bcol = ((lane >> 3) & 1) << 2;
    #pragma unroll
    for (int ks = 0; ks < 2; ++ks) {
        const int k2b = ks * 8;
        u32 ah[4][4], al[4][4];
        #pragma unroll
        for (int mi = 0; mi < 4; ++mi) {
            const int r = wm * 64 + mi * 16 + arow;
            ldmat_x4(ah[mi], Ah + r * LDT + k2b + acol);
            ldmat_x4(al[mi], Al + r * LDT + k2b + acol);
        }
        #pragma unroll
        for (int ni = 0; ni < 5; ++ni) {
            const int nr = wn * 40 + ni * 8 + brow;
            u32 bh[2], bl[2];
            ldmat_x2(bh, Bh + nr * LDT + k2b + bcol);
            ldmat_x2(bl, Bl + nr * LDT + k2b + bcol);
            #pragma unroll
            for (int mi = 0; mi < 4; ++mi) {
                mma16816(acc[mi][ni], ah[mi], bh);
                mma16816(acc[mi][ni], al[mi], bh);
                mma16816(acc[mi][ni], ah[mi], bl);
            }
        }
    }
}
// trans A: smem [K=32 rows][M=128 u16 cols], stride LDTT
__device__ __forceinline__ void tile_mma_t(
    const u32* Ah, const u32* Al, const u32* Bh, const u32* Bl,
    float (*acc)[5][4], int wm, int wn, int lane)
{
    const int kr = (lane & 7) + ((lane >> 4) << 3);
    const int mo = ((lane >> 3) & 1) << 3;
    const int brow = lane & 7, bcol = ((lane >> 3) & 1) << 2;
    #pragma unroll
    for (int ks = 0; ks < 2; ++ks) {
        const int k2b = ks * 8;
        u32 ah[4][4], al[4][4];
        #pragma unroll
        for (int mi = 0; mi < 4; ++mi) {
            const int m = wm * 64 + mi * 16 + mo;
            ldmat_x4t(ah[mi], (const u16*)(Ah + (ks * 16 + kr) * LDTT) + m);
            ldmat_x4t(al[mi], (const u16*)(Al + (ks * 16 + kr) * LDTT) + m);
        }
        #pragma unroll
        for (int ni = 0; ni < 5; ++ni) {
            const int nr = wn * 40 + ni * 8 + brow;
            u32 bh[2], bl[2];
            ldmat_x2(bh, Bh + nr * LDT + k2b + bcol);
            ldmat_x2(bl, Bl + nr * LDT + k2b + bcol);
            #pragma unroll
            for (int mi = 0; mi < 4; ++mi) {
                mma16816(acc[mi][ni], ah[mi], bh);
                mma16816(acc[mi][ni], al[mi], bh);
                mma16816(acc[mi][ni], ah[mi], bl);
            }
        }
    }
}

// B fill via cp.async from u16 hi/lo arrays with row stride rs (u16 units)
__device__ __forceinline__ void cpB(u32* buf, int t, const u16* bh, const u16* bl,
                                    long rs, long colbase) {
    #pragma unroll
    for (int ii = 0; ii < 5; ++ii) {
        int i = t + 256 * ii;          // 0..1279
        int arr = i >= 640;
        int j = arr ? i - 640 : i;
        int row = j >> 2, q = j & 3;
        const u16* s = (arr ? bl : bh) + (long)row * rs + colbase + q * 8;
        char* d = (char*)(buf + 2 * SA + arr * SB) + row * 80 + q * 16;
        cpa16(d, s, 16);
    }
}
__device__ __forceinline__ void cpB_t(u32* buf, int t, const u16* bh, const u16* bl,
                                      long rs, long colbase) {
    #pragma unroll
    for (int ii = 0; ii < 5; ++ii) {
        int i = t + 256 * ii;
        int arr = i >= 640;
        int j = arr ? i - 640 : i;
        int row = j >> 2, q = j & 3;
        const u16* s = (arr ? bl : bh) + (long)row * rs + colbase + q * 8;
        char* d = (char*)(buf + 2 * SAT + arr * SB) + row * 80 + q * 16;
        cpa16(d, s, 16);
    }
}

// ===========================================================================
// GEMM1: D[n=128,k=160] = x^T·cls ; manual A (also emits xh/xl), cp.async B.
// ===========================================================================
__device__ __forceinline__ void g1_storeA(u32* buf, int n, int half, const float* pxa,
                                          u16* xh, u16* xl, long gbase) {
    u32 hvs[8], lvs[8];
    #pragma unroll
    for (int j = 0; j < 8; ++j) split2(pxa[2 * j], pxa[2 * j + 1], &hvs[j], &lvs[j]);
    u32* a = buf + n * LDT + half * 8;
    *(uint4*)(a)     = make_uint4(hvs[0], hvs[1], hvs[2], hvs[3]);
    *(uint4*)(a + 4) = make_uint4(hvs[4], hvs[5], hvs[6], hvs[7]);
    u32* b = buf + SA + n * LDT + half * 8;
    *(uint4*)(b)     = make_uint4(lvs[0], lvs[1], lvs[2], lvs[3]);
    *(uint4*)(b + 4) = make_uint4(lvs[4], lvs[5], lvs[6], lvs[7]);
    #pragma unroll
    for (int j = 0; j < 8; ++j) {
        long o = gbase + (long)(2 * j) * HW;
        xh[o]      = (u16)(hvs[j] & 0xFFFF);
        xh[o + HW] = (u16)(hvs[j] >> 16);
        xl[o]      = (u16)(lvs[j] & 0xFFFF);
        xl[o + HW] = (u16)(lvs[j] >> 16);
    }
}

__global__ __launch_bounds__(256) void k_gemm1_mma(
    const float* __restrict__ x, const u16* __restrict__ clsh, const u16* __restrict__ clsl,
    u16* __restrict__ Eh, u16* __restrict__ El,
    u16* __restrict__ xh, u16* __restrict__ xl,
    float* __restrict__ colinv, float* __restrict__ rowpart)
{
    extern __shared__ u32 sm[];
    float* srow  = (float*)(sm + 2 * BUF_N);
    float* skrow = srow + 128;
    const int t = threadIdx.x;
    const int wid = t >> 5, lane = t & 31, g = lane >> 2, tid = lane & 3;
    const int wm = wid >> 2, wn = wid & 3;
    const int n0 = blockIdx.x * 128, b = blockIdx.y;
    if (t < 128) srow[t] = 0.f;
    if (t < KPAD) skrow[t] = 0.f;

    float acc[4][5][4] = {};
    const int n = t & 127, half = t >> 7;
    const float* xb = x + (long)b * C * HW + n0 + n;

    float pxa[16];
    #pragma unroll
    for (int j = 0; j < 8; ++j) {
        int c = (half * 8 + j) * 2;
        pxa[2 * j] = xb[(long)c * HW]; pxa[2 * j + 1] = xb[(long)(c + 1) * HW];
    }
    g1_storeA(sm, n, half, pxa, xh, xl,
              ((long)b * C + half * 16) * HW + n0 + n);
    cpB(sm, t, clsh, clsl, C, 0);
    CP_COMMIT(); CP_WAIT0();
    __syncthreads();

    #pragma unroll 1
    for (int cc = 0; cc < C / KC; ++cc) {
        if (cc + 1 < C / KC) {
            #pragma unroll
            for (int j = 0; j < 8; ++j) {
                int c = (cc + 1) * KC + (half * 8 + j) * 2;
                pxa[2 * j] = xb[(long)c * HW]; pxa[2 * j + 1] = xb[(long)(c + 1) * HW];
            }
            u32* nb = sm + ((cc + 1) & 1) * BUF_N;
            cpB(nb, t, clsh, clsl, C, (cc + 1) * 32);
            CP_COMMIT();
        }
        u32* cb_ = sm + (cc & 1) * BUF_N;
        tile_mma(cb_, cb_ + SA, cb_ + 2 * SA, cb_ + 2 * SA + SB, acc, wm, wn, lane);
        if (cc + 1 < C / KC) {
            u32* nb = sm + ((cc + 1) & 1) * BUF_N;
            g1_storeA(nb, n, half, pxa, xh, xl,
                      ((long)b * C + (cc + 1) * 32 + half * 16) * HW + n0 + n);
            CP_WAIT0();
            __syncthreads();
        }
    }

    #pragma unroll
    for (int mi = 0; mi < 4; ++mi) {
        const int r0 = wm * 64 + mi * 16 + g;
        float s0 = 0.f, s1 = 0.f;
        #pragma unroll
        for (int ni = 0; ni < 5; ++ni) {
            const int cb = wn * 40 + ni * 8 + tid * 2;
            float e0 = __expf(acc[mi][ni][0]);
            float e1 = __expf(acc[mi][ni][1]);
            float e2 = __expf(acc[mi][ni][2]);
            float e3 = __expf(acc[mi][ni][3]);
            float vk0 = 0.f, vk1 = 0.f;
            if (cb < KCLS) {
                long o0 = ((long)b * KCLS + cb) * HW + n0 + r0;
                u32 u = __float_as_uint(e0);
                Eh[o0] = (u16)(u >> 16);
                El[o0] = (u16)(__float_as_uint(e0 - __uint_as_float(u & 0xFFFF0000u)) >> 16);
                u = __float_as_uint(e2);
                Eh[o0 + 8] = (u16)(u >> 16);
                El[o0 + 8] = (u16)(__float_as_uint(e2 - __uint_as_float(u & 0xFFFF0000u)) >> 16);
                s0 += e0; s1 += e2; vk0 = e0 + e2;
            }
            if (cb + 1 < KCLS) {
                long o1 = ((long)b * KCLS + cb + 1) * HW + n0 + r0;
                u32 u = __float_as_uint(e1);
                Eh[o1] = (u16)(u >> 16);
                El[o1] = (u16)(__float_as_uint(e1 - __uint_as_float(u & 0xFFFF0000u)) >> 16);
                u = __float_as_uint(e3);
                Eh[o1 + 8] = (u16)(u >> 16);
                El[o1 + 8] = (u16)(__float_as_uint(e3 - __uint_as_float(u & 0xFFFF0000u)) >> 16);
                s0 += e1; s1 += e3; vk1 = e1 + e3;
            }
            vk0 += __shfl_xor_sync(0xFFFFFFFFu, vk0, 4);
            vk0 += __shfl_xor_sync(0xFFFFFFFFu, vk0, 8);
            vk0 += __shfl_xor_sync(0xFFFFFFFFu, vk0, 16);
            vk1 += __shfl_xor_sync(0xFFFFFFFFu, vk1, 4);
            vk1 += __shfl_xor_sync(0xFFFFFFFFu, vk1, 8);
            vk1 += __shfl_xor_sync(0xFFFFFFFFu, vk1, 16);
            if (g == 0 && cb < KCLS) {
                atomicAdd(&skrow[cb], vk0);
                if (cb + 1 < KCLS) atomicAdd(&skrow[cb + 1], vk1);
            }
        }
        atomicAdd(&srow[r0], s0);
        atomicAdd(&srow[r0 + 8], s1);
    }
    __syncthreads();
    if (t < 128) colinv[(long)b * HW + n0 + t] = 1.f / srow[t];
    if (t < KPAD)
        rowpart[((long)b * KPAD + t) * (HW / 128) + blockIdx.x] = skrow[t];
}

// ===========================================================================
// pool: D[c=128,k=160] = sum_n x[c,n]*E[k,n] — all fills cp.async.
// ===========================================================================
__device__ __forceinline__ void pool_fill(u32* buf, int t, int b, int c0, int nb,
                                          const u16* xh, const u16* xl,
                                          const u16* Eh, const u16* El) {
    #pragma unroll
    for (int ii = 0; ii < 4; ++ii) {
        int i = t + 256 * ii;
        int arr = i >> 9;
        int j = i & 511;
        int row = j >> 2, q = j & 3;
        const u16* s = (arr ? xl : xh) + ((long)b * C + c0 + row) * HW + nb + q * 8;
        char* d = (char*)(buf + arr * SA) + row * 80 + q * 16;
        cpa16(d, s, 16);
    }
    #pragma unroll
    for (int ii = 0; ii < 5; ++ii) {
        int i = t + 256 * ii;
        int arr = i >= 640;
        int j = arr ? i - 640 : i;
        int row = j >> 2, q = j & 3;
        int rc = row < KCLS ? row : KCLS - 1;
        const u16* s = (arr ? El : Eh) + ((long)b * KCLS + rc) * HW + nb + q * 8;
        char* d = (char*)(buf + 2 * SA + arr * SB) + row * 80 + q * 16;
        cpa16(d, s, row < KCLS ? 16u : 0u);
    }
}

__global__ __launch_bounds__(256, 2) void k_pool_mma(
    const u16* __restrict__ xh, const u16* __restrict__ xl,
    const u16* __restrict__ Eh, const u16* __restrict__ El,
    float* __restrict__ poolpart)
{
    extern __shared__ u32 sm[];
    const int t = threadIdx.x;
    const int wid = t >> 5, lane = t & 31, g = lane >> 2, tid = lane & 3;
    const int wm = wid >> 2, wn = wid & 3;
    const int c0 = blockIdx.x * 128, sp = blockIdx.y, b = blockIdx.z;
    const int nbase = sp * (HW / NSPLIT);
    const int NCH = (HW / NSPLIT) / KC;
    float acc[4][5][4] = {};

    pool_fill(sm, t, b, c0, nbase, xh, xl, Eh, El);
    CP_COMMIT(); CP_WAIT0();
    __syncthreads();

    #pragma unroll 1
    for (int cc = 0; cc < NCH; ++cc) {
        if (cc + 1 < NCH) {
            pool_fill(sm + ((cc + 1) & 1) * BUF_N, t, b, c0, nbase + (cc + 1) * KC,
                      xh, xl, Eh, El);
            CP_COMMIT();
        }
        u32* cb_ = sm + (cc & 1) * BUF_N;
        tile_mma(cb_, cb_ + SA, cb_ + 2 * SA, cb_ + 2 * SA + SB, acc, wm, wn, lane);
        if (cc + 1 < NCH) { CP_WAIT0(); __syncthreads(); }
    }

    const long base = ((long)sp * BATCH + b) * KCLS;
    #pragma unroll
    for (int mi = 0; mi < 4; ++mi) {
        const int r0 = wm * 64 + mi * 16 + g;
        #pragma unroll
        for (int ni = 0; ni < 5; ++ni) {
            const int cb = wn * 40 + ni * 8 + tid * 2;
            if (cb < KCLS) {
                poolpart[(base + cb) * C + c0 + r0]     = acc[mi][ni][0];
                poolpart[(base + cb) * C + c0 + r0 + 8] = acc[mi][ni][2];
            }
            if (cb + 1 < KCLS) {
                poolpart[(base + cb + 1) * C + c0 + r0]     = acc[mi][ni][1];
                poolpart[(base + cb + 1) * C + c0 + r0 + 8] = acc[mi][ni][3];
            }
        }
    }
}

// ===========================================================================
// masks: phase2 (E·G) first, scale by ci, then phase1 (x^T·acls); LN epilogue.
// All fills cp.async; A via trans-ldmatrix.
// ===========================================================================
__device__ __forceinline__ void masks_fillA(u32* buf, int t, const u16* ah_, const u16* al_,
                                            long rowbase, long rowlimit, long stride,
                                            long colbase) {
    #pragma unroll
    for (int ii = 0; ii < 4; ++ii) {
        int i = t + 256 * ii;
        int arr = i >> 9;
        int j = i & 511;
        int row = j >> 4, q = j & 15;
        long r = rowbase + row;
        long rc = r < rowlimit ? r : rowlimit - 1;
        const u16* s = (arr ? al_ : ah_) + rc * stride + colbase + q * 8;
        char* d = (char*)(buf + arr * SAT) + row * (LDTT * 4) + q * 16;
        cpa16(d, s, r < rowlimit ? 16u : 0u);
    }
}

__global__ __launch_bounds__(256, 2) void k_masks_mma(
    const u16* __restrict__ xh, const u16* __restrict__ xl,
    const u16* __restrict__ aclsh, const u16* __restrict__ aclsl,
    const u16* __restrict__ Gh, const u16* __restrict__ Gl,
    const u16* __restrict__ Eh, const u16* __restrict__ El,
    const float* __restrict__ colinv,
    const float* __restrict__ gamma, const float* __restrict__ beta,
    float* __restrict__ out)
{
    extern __shared__ u32 sm[];
    float* ssum = (float*)(sm + 2 * BUF_T);
    float* ssq  = ssum + 128;
    float* civ  = ssq + 128;
    const int t = threadIdx.x;
    const int wid = t >> 5, lane = t & 31, g = lane >> 2, tid = lane & 3;
    const int wm = wid >> 2, wn = wid & 3;
    const int n0 = blockIdx.x * 128, b = blockIdx.y;
    if (t < 128) {
        ssum[t] = 0.f; ssq[t] = 0.f;
        civ[t] = colinv[(long)b * HW + n0 + t];
    }

    float acc[4][5][4] = {};
    const u16* ab_h = aclsh + (long)b * KPAD * C;
    const u16* ab_l = aclsl + (long)b * KPAD * C;
    const u16* gb_h = Gh + (long)b * KPAD * KP2;
    const u16* gb_l = Gl + (long)b * KPAD * KP2;
    const long eb = (long)b * KCLS;
    const long xbge = (long)b * C;
    const int NCH2 = KP2 / KC;          // 6 (phase 2 first)
    const int NCH  = NCH2 + C / KC;     // 22

    // chunk 0 = phase-2 chunk 0
    masks_fillA(sm, t, Eh + (long)0, El, eb + 0, eb + KCLS, HW, n0);
    cpB_t(sm, t, gb_h, gb_l, KP2, 0);
    CP_COMMIT(); CP_WAIT0();
    __syncthreads();

    #pragma unroll 1
    for (int j = 0; j < NCH; ++j) {
        const int jn = j + 1;
        if (jn < NCH) {
            u32* nb = sm + (jn & 1) * BUF_T;
            if (jn < NCH2) {
                masks_fillA(nb, t, Eh, El, eb + jn * 32, eb + KCLS, HW, n0);
                cpB_t(nb, t, gb_h, gb_l, KP2, jn * 32);
            } else {
                const int cc = jn - NCH2;
                masks_fillA(nb, t, xh, xl, xbge + cc * 32, xbge + C, HW, n0);
                cpB_t(nb, t, ab_h, ab_l, C, cc * 32);
            }
            CP_COMMIT();
        }
        u32* cb_ = sm + (j & 1) * BUF_T;
        tile_mma_t(cb_, cb_ + SAT, cb_ + 2 * SAT, cb_ + 2 * SAT + SB, acc, wm, wn, lane);
        if (j == NCH2 - 1) {
            // scale phase-2 partial by ci[n]
            #pragma unroll
            for (int mi = 0; mi < 4; ++mi) {
                const int r0 = wm * 64 + mi * 16 + g;
                const float c0v = civ[r0], c1v = civ[r0 + 8];
                #pragma unroll
                for (int ni = 0; ni < 5; ++ni) {
                    acc[mi][ni][0] *= c0v; acc[mi][ni][1] *= c0v;
                    acc[mi][ni][2] *= c1v; acc[mi][ni][3] *= c1v;
                }
            }
        }
        if (jn < NCH) { CP_WAIT0(); __syncthreads(); }
    }

    // LayerNorm over k (<150)
    #pragma unroll
    for (int mi = 0; mi < 4; ++mi) {
        const int r0 = wm * 64 + mi * 16 + g;
        float s0 = 0.f, q0 = 0.f, s1 = 0.f, q1 = 0.f;
        #pragma unroll
        for (int ni = 0; ni < 5; ++ni) {
            const int cb = wn * 40 + ni * 8 + tid * 2;
            if (cb < KCLS) {
                float v = acc[mi][ni][0]; s0 += v; q0 += v * v;
                v = acc[mi][ni][2]; s1 += v; q1 += v * v;
            }
            if (cb + 1 < KCLS) {
                float v = acc[mi][ni][1]; s0 += v; q0 += v * v;
                v = acc[mi][ni][3]; s1 += v; q1 += v * v;
            }
        }
        atomicAdd(&ssum[r0], s0); atomicAdd(&ssq[r0], q0);
        atomicAdd(&ssum[r0 + 8], s1); atomicAdd(&ssq[r0 + 8], q1);
    }
    __syncthreads();
    #pragma unroll
    for (int mi = 0; mi < 4; ++mi) {
        const int r0 = wm * 64 + mi * 16 + g;
        const float mu0 = ssum[r0] * (1.f / KCLS);
        const float rs0 = rsqrtf(ssq[r0] * (1.f / KCLS) - mu0 * mu0 + 1e-5f);
        const float mu1 = ssum[r0 + 8] * (1.f / KCLS);
        const float rs1 = rsqrtf(ssq[r0 + 8] * (1.f / KCLS) - mu1 * mu1 + 1e-5f);
        #pragma unroll
        for (int ni = 0; ni < 5; ++ni) {
            const int cb = wn * 40 + ni * 8 + tid * 2;
            if (cb < KCLS) {
                float ga = gamma[cb], be = beta[cb];
                out[((long)b * KCLS + cb) * HW + n0 + r0] =
                    (acc[mi][ni][0] - mu0) * rs0 * ga + be;
                out[((long)b * KCLS + cb) * HW + n0 + r0 + 8] =
                    (acc[mi][ni][2] - mu1) * rs1 * ga + be;
            }
            if (cb + 1 < KCLS) {
                float ga = gamma[cb + 1], be = beta[cb + 1];
                out[((long)b * KCLS + cb + 1) * HW + n0 + r0] =
                    (acc[mi][ni][1] - mu0) * rs0 * ga + be;
                out[((long)b * KCLS + cb + 1) * HW + n0 + r0 + 8] =
                    (acc[mi][ni][3] - mu1) * rs1 * ga + be;
            }
        }
    }
}

// ===========================================================================
// SIMT small kernels
// ===========================================================================
__global__ void k_prep(const float* __restrict__ cls, u16* __restrict__ ch_, u16* __restrict__ cl_)
{
    int i = blockIdx.x * 256 + threadIdx.x;
    if (i < KPAD * C) {
        float v = (i < KCLS * C) ? cls[i] : 0.f;
        u32 u = __float_as_uint(v);
        float l = v - __uint_as_float(u & 0xFFFF0000u);
        ch_[i] = (u16)(u >> 16);
        cl_[i] = (u16)(__float_as_uint(l) >> 16);
    }
}

__global__ void k_rowred(const float* __restrict__ rowpart, float* __restrict__ rinv)
{
    int idx = blockIdx.x * 256 + threadIdx.x;
    if (idx < BATCH * KPAD) {
        const float* p = rowpart + (long)idx * (HW / 128);
        float s = 0.f;
        for (int i = 0; i < HW / 128; ++i) s += p[i];
        rinv[idx] = 1.f / s;
    }
}

__device__ __forceinline__ void sg_body(
    const float* __restrict__ A, int arow_valid, const float* __restrict__ W, int brow_valid,
    float acc[4][4], int t, float As[16][64], float Bs[16][64])
{
    const int tm = (t >> 4) * 4, tn = (t & 15) * 4;
    const int ar = t >> 2, ac = (t & 3) * 4;
    const int bc = t >> 2, bp = (t & 3) * 4;
    for (int p0 = 0; p0 < C; p0 += 16) {
        float4 av = make_float4(0.f, 0.f, 0.f, 0.f);
        if (ar < arow_valid) av = *(const float4*)&A[(long)ar * C + p0 + ac];
        As[ac + 0][ar] = av.x; As[ac + 1][ar] = av.y; As[ac + 2][ar] = av.z; As[ac + 3][ar] = av.w;
        float4 bv = make_float4(0.f, 0.f, 0.f, 0.f);
        if (bc < brow_valid) bv = *(const float4*)&W[(long)bc * C + p0 + bp];
        Bs[bp + 0][bc] = bv.x; Bs[bp + 1][bc] = bv.y; Bs[bp + 2][bc] = bv.z; Bs[bp + 3][bc] = bv.w;
        __syncthreads();
        #pragma unroll
        for (int kk = 0; kk < 16; ++kk) {
            float4 a4 = *(const float4*)&As[kk][tm];
            float4 b4 = *(const float4*)&Bs[kk][tn];
            float aa[4] = {a4.x, a4.y, a4.z, a4.w};
            float bb[4] = {b4.x, b4.y, b4.z, b4.w};
            #pragma unroll
            for (int i = 0; i < 4; ++i)
                #pragma unroll
                for (int j = 0; j < 4; ++j)
                    acc[i][j] = fmaf(aa[i], bb[j], acc[i][j]);
        }
        __syncthreads();
    }
}

__global__ __launch_bounds__(256) void k_clsWf(
    const float* __restrict__ cls, const float* __restrict__ W, float* __restrict__ outw)
{
    __shared__ float As[16][64], Bs[16][64];
    const int t = threadIdx.x, k0 = blockIdx.x * 64, c0 = blockIdx.y * 64;
    float acc[4][4] = {};
    int av = KCLS - k0; av = av > 64 ? 64 : (av > 0 ? av : 0);
    sg_body(cls + (long)k0 * C, av, W + (long)c0 * C, 64, acc, t, As, Bs);
    const int tm = (t >> 4) * 4, tn = (t & 15) * 4;
    #pragma unroll
    for (int i = 0; i < 4; ++i) {
        int k = k0 + tm + i;
        if (k < KCLS)
            *(float4*)&outw[(long)k * C + c0 + tn] =
                make_float4(acc[i][0], acc[i][1], acc[i][2], acc[i][3]);
    }
}

__global__ __launch_bounds__(256) void k_acls(
    const float* __restrict__ poolpart, const float* __restrict__ rinv,
    const float* __restrict__ W, const float* __restrict__ cls,
    float* __restrict__ outf, u16* __restrict__ outh, u16* __restrict__ outl)
{
    __shared__ float As[16][64], Bs[16][64];
    const int t = threadIdx.x;
    const int k0 = blockIdx.x * 64, c0 = blockIdx.y * 64, b = blockIdx.z;
    const int tm = (t >> 4) * 4, tn = (t & 15) * 4;
    const int ar = t >> 2, ac = (t & 3) * 4;
    const int bc = t >> 2, bp = (t & 3) * 4;
    float acc[4][4] = {};
    const int ka = k0 + ar;
    const float rv = (ka < KCLS) ? rinv[b * KPAD + ka] : 0.f;

    for (int p0 = 0; p0 < C; p0 += 16) {
        float4 av = make_float4(0.f, 0.f, 0.f, 0.f);
        if (ka < KCLS) {
            #pragma unroll
            for (int s = 0; s < NSPLIT; ++s) {
                float4 v = *(const float4*)
                    &poolpart[(((long)s * BATCH + b) * KCLS + ka) * C + p0 + ac];
                av.x += v.x; av.y += v.y; av.z += v.z; av.w += v.w;
            }
            av.x *= rv; av.y *= rv; av.z *= rv; av.w *= rv;
        }
        As[ac + 0][ar] = av.x; As[ac + 1][ar] = av.y; As[ac + 2][ar] = av.z; As[ac + 3][ar] = av.w;
        float4 bv = *(const float4*)&W[(long)(c0 + bc) * C + p0 + bp];
        Bs[bp + 0][bc] = bv.x; Bs[bp + 1][bc] = bv.y; Bs[bp + 2][bc] = bv.z; Bs[bp + 3][bc] = bv.w;
        __syncthreads();
        #pragma unroll
        for (int kk = 0; kk < 16; ++kk) {
            float4 a4 = *(const float4*)&As[kk][tm];
            float4 b4 = *(const float4*)&Bs[kk][tn];
            float aa[4] = {a4.x, a4.y, a4.z, a4.w};
            float bb[4] = {b4.x, b4.y, b4.z, b4.w};
            #pragma unroll
            for (int i = 0; i < 4; ++i)
                #pragma unroll
                for (int j = 0; j < 4; ++j)
                    acc[i][j] = fmaf(aa[i], bb[j], acc[i][j]);
        }
        __syncthreads();
    }
    #pragma unroll
    for (int i = 0; i < 4; ++i) {
        int k = k0 + tm + i;
        if (k < KCLS) {
            #pragma unroll
            for (int j = 0; j < 4; ++j) {
                float v = acc[i][j] + cls[(long)k * C + c0 + tn + j];
                outf[((long)b * KCLS + k) * C + c0 + tn + j] = v;
                long po = ((long)b * KPAD + k) * C + c0 + tn + j;
                u32 u = __float_as_uint(v);
                float l = v - __uint_as_float(u & 0xFFFF0000u);
                outh[po] = (u16)(u >> 16);
                outl[po] = (u16)(__float_as_uint(l) >> 16);
            }
        } else if (k < KPAD) {
            #pragma unroll
            for (int j = 0; j < 4; ++j) {
                long po = ((long)b * KPAD + k) * C + c0 + tn + j;
                outh[po] = 0; outl[po] = 0;
            }
        }
    }
}

__global__ __launch_bounds__(256) void k_G(
    const float* __restrict__ acls, const float* __restrict__ clsWf,
    u16* __restrict__ Gh, u16* __restrict__ Gl)
{
    __shared__ float As[16][64], Bs[16][64];
    const int t = threadIdx.x;
    const int k0 = blockIdx.x * 64, k20 = blockIdx.y * 64, b = blockIdx.z;
    float acc[4][4] = {};
    int av = KCLS - k0; av = av > 64 ? 64 : (av > 0 ? av : 0);
    int bv = KCLS - k20; bv = bv > 64 ? 64 : (bv > 0 ? bv : 0);
    sg_body(acls + ((long)b * KCLS + k0) * C, av, clsWf + (long)k20 * C, bv, acc, t, As, Bs);
    const int tm = (t >> 4) * 4, tn = (t & 15) * 4;
    #pragma unroll
    for (int i = 0; i < 4; ++i) {
        int k = k0 + tm + i;
        if (k < KPAD) {
            #pragma unroll
            for (int j = 0; j < 4; ++j) {
                float v = acc[i][j];
                long po = ((long)b * KPAD + k) * KP2 + k20 + tn + j;
                u32 u = __float_as_uint(v);
                float l = v - __uint_as_float(u & 0xFFFF0000u);
                Gh[po] = (u16)(u >> 16);
                Gl[po] = (u16)(__float_as_uint(l) >> 16);
            }
        }
    }
}

// ===========================================================================
extern "C" void kernel_launch(void* const* d_in, const int* in_sizes, int n_in,
                              void* d_out, int out_size)
{
    const float* x     = (const float*)d_in[0];
    const float* cls   = (const float*)d_in[1];
    const float* Wcls  = (const float*)d_in[2];
    const float* Wfeat = (const float*)d_in[3];
    const float* gamma = (const float*)d_in[4];
    const float* beta  = (const float*)d_in[5];
    float* out = (float*)d_out;

    u16 *clsh, *clsl, *aclsh, *aclsl, *Gh, *Gl, *Eh, *El, *xh, *xl;
    float *colinv, *rowpart, *rinv, *poolpart, *acls, *clsWf;
    cudaGetSymbolAddress((void**)&clsh,  g_clsh);
    cudaGetSymbolAddress((void**)&clsl,  g_clsl);
    cudaGetSymbolAddress((void**)&Eh,    g_Eh);
    cudaGetSymbolAddress((void**)&El,    g_El);
    cudaGetSymbolAddress((void**)&xh,    g_xh);
    cudaGetSymbolAddress((void**)&xl,    g_xl);
    cudaGetSymbolAddress((void**)&colinv, g_colinv);
    cudaGetSymbolAddress((void**)&rowpart, g_rowpart);
    cudaGetSymbolAddress((void**)&rinv,  g_rinv);
    cudaGetSymbolAddress((void**)&poolpart, g_poolpart);
    cudaGetSymbolAddress((void**)&acls,  g_acls);
    cudaGetSymbolAddress((void**)&aclsh, g_aclsh);
    cudaGetSymbolAddress((void**)&aclsl, g_aclsl);
    cudaGetSymbolAddress((void**)&clsWf, g_clsWf);
    cudaGetSymbolAddress((void**)&Gh,    g_Gh);
    cudaGetSymbolAddress((void**)&Gl,    g_Gl);

    cudaFuncSetAttribute(k_gemm1_mma, cudaFuncAttributeMaxDynamicSharedMemorySize, SMEM_N);
    cudaFuncSetAttribute(k_pool_mma,  cudaFuncAttributeMaxDynamicSharedMemorySize, SMEM_N);
    cudaFuncSetAttribute(k_masks_mma, cudaFuncAttributeMaxDynamicSharedMemorySize, SMEM_T);

    k_prep<<<(KPAD * C + 255) / 256, 256>>>(cls, clsh, clsl);
    k_gemm1_mma<<<dim3(HW / 128, BATCH), 256, SMEM_N>>>(
        x, clsh, clsl, Eh, El, xh, xl, colinv, rowpart);
    k_rowred<<<(BATCH * KPAD + 255) / 256, 256>>>(rowpart, rinv);
    k_pool_mma<<<dim3(C / 128, NSPLIT, BATCH), 256, SMEM_N>>>(xh, xl, Eh, El, poolpart);
    k_clsWf<<<dim3(3, C / 64), 256>>>(cls, Wfeat, clsWf);
    k_acls<<<dim3(3, C / 64, BATCH), 256>>>(poolpart, rinv, Wcls, cls, acls, aclsh, aclsl);
    k_G<<<dim3(3, 3, BATCH), 256>>>(acls, clsWf, Gh, Gl);
    k_masks_mma<<<dim3(HW / 128, BATCH), 256, SMEM_T>>>(
        xh, xl, aclsh, aclsl, Gh, Gl, Eh, El, colinv, gamma, beta, out);
}